// round 2
// baseline (speedup 1.0000x reference)
#include <cuda_runtime.h>

// ============================================================================
// Forecaster: per-(b,s) independent 2-step, 2-layer LSTM + FC head.
// M = 65536 rows. All GEMMs fp32 FFMA (round-1 correctness baseline).
//
// Stage 1: G = x1 @ Wih0^T + bias0          -> h1, c1       (K=64)
// Stage 2: G = mug[b] + h1 @ Whh0^T         -> h2 (uses c1) (K=128)
// Stage 3: G = h1 @ Wih1^T + bias1          -> h1p, c1p     (K=128)
// Stage 4: G = h2 @ Wih1^T + h1p @ Whh1^T + bias1 -> relu(h2p) (K=128+128)
// FC:      out = relu(h2p) . fc_w + fc_b
// ============================================================================

#define NROWS 65536   // B*S
#define HDIM  128
#define G4    512     // 4*H
#define FDIM  64

// -------- device scratch (static: allocation-free) --------
__device__ float d_WT0i[64 * 512];    // W_ih0^T  [K=64][512]
__device__ float d_WT0h[128 * 512];   // W_hh0^T  [K=128][512]
__device__ float d_WT1i[128 * 512];   // W_ih1^T
__device__ float d_WT1h[128 * 512];   // W_hh1^T
__device__ float d_bias0[512];
__device__ float d_bias1[512];
__device__ float d_mug[64 * 512];     // mu @ Wih0^T + bias0, per batch b

__device__ float d_h1 [NROWS * HDIM];
__device__ float d_c1 [NROWS * HDIM];
__device__ float d_h2 [NROWS * HDIM];
__device__ float d_h1p[NROWS * HDIM];
__device__ float d_c1p[NROWS * HDIM];
__device__ float d_h2p[NROWS * HDIM];

// -------- fast, overflow-safe activations (fp32, ~1e-6 rel err) --------
__device__ __forceinline__ float sigm_f(float x) {
    return __fdividef(1.0f, 1.0f + __expf(-x));
}
__device__ __forceinline__ float tanh_f(float x) {
    // 2*sigmoid(2x)-1 : safe at both tails with __expf
    return __fdividef(2.0f, 1.0f + __expf(-2.0f * x)) - 1.0f;
}

// ============================================================================
// Prep kernels
// ============================================================================
__global__ void prep_transpose(const float* __restrict__ Wih0,
                               const float* __restrict__ Whh0,
                               const float* __restrict__ Wih1,
                               const float* __restrict__ Whh1,
                               const float* __restrict__ bih0,
                               const float* __restrict__ bhh0,
                               const float* __restrict__ bih1,
                               const float* __restrict__ bhh1) {
    int idx = blockIdx.x * blockDim.x + threadIdx.x;   // grid covers 512*128
    if (idx < 512 * 128) {
        int g = idx / 128;
        int k = idx % 128;
        d_WT0h[k * 512 + g] = Whh0[g * 128 + k];
        d_WT1i[k * 512 + g] = Wih1[g * 128 + k];
        d_WT1h[k * 512 + g] = Whh1[g * 128 + k];
        if (k < 64) d_WT0i[k * 512 + g] = Wih0[g * 64 + k];
    }
    if (idx < 512) {
        d_bias0[idx] = bih0[idx] + bhh0[idx];
        d_bias1[idx] = bih1[idx] + bhh1[idx];
    }
}

__global__ void prep_mug(const float* __restrict__ mu,
                         const float* __restrict__ Wih0) {
    // block = one batch b (512 threads, one per gate column)
    __shared__ float mur[64];
    int g = threadIdx.x;
    if (g < 64) mur[g] = mu[blockIdx.x * 64 + g];
    __syncthreads();
    float s = d_bias0[g];
    const float* wr = Wih0 + g * 64;
#pragma unroll
    for (int k = 0; k < 64; k++) s = fmaf(mur[k], wr[k], s);
    d_mug[blockIdx.x * 512 + g] = s;
}

// ============================================================================
// GEMM source accumulation: acc[i][g][jj] += A[row][k] * WT[k][g*128+j]
// CTA tile: 128 rows x 32 h-cols (x 4 gates). Thread tile: 8 rows x 2 cols x 4 gates.
// ============================================================================
template <int KSRC>
__device__ __forceinline__ void gemm_source(const float* __restrict__ Ag,
                                            const float* __restrict__ Wg,
                                            int row0, int j0, int tx, int ty, int tid,
                                            float (&acc)[8][4][2],
                                            float (&As)[32][129],
                                            float (&Ws)[32][128]) {
    for (int kc = 0; kc < KSRC; kc += 32) {
        __syncthreads();
        // ---- load A chunk: 128 rows x 32 k (1024 float4) ----
#pragma unroll
        for (int it = 0; it < 4; it++) {
            int e = tid + 256 * it;         // float4 index
            int r = e >> 3;                 // 8 float4 per row
            int q = e & 7;
            float4 v = *reinterpret_cast<const float4*>(
                Ag + (size_t)(row0 + r) * KSRC + kc + q * 4);
            int kk = q * 4;
            As[kk + 0][r] = v.x;
            As[kk + 1][r] = v.y;
            As[kk + 2][r] = v.z;
            As[kk + 3][r] = v.w;
        }
        // ---- load W chunk: 32 k x (4 gates x 32 j) (1024 float4) ----
#pragma unroll
        for (int it = 0; it < 4; it++) {
            int e  = tid + 256 * it;
            int kk = e >> 5;                // 32 float4 per k-row
            int c4 = e & 31;
            int rem = c4 * 4;               // float offset within [0,128)
            int g  = rem >> 5;
            int jj = rem & 31;
            float4 v = *reinterpret_cast<const float4*>(
                Wg + (size_t)(kc + kk) * 512 + g * 128 + j0 + jj);
            *reinterpret_cast<float4*>(&Ws[kk][rem]) = v;
        }
        __syncthreads();
        // ---- FMA inner loop ----
#pragma unroll 8
        for (int kk = 0; kk < 32; kk++) {
            float a[8];
#pragma unroll
            for (int i = 0; i < 8; i++) a[i] = As[kk][ty * 8 + i];
            float w[4][2];
#pragma unroll
            for (int g = 0; g < 4; g++) {
                float2 wv = *reinterpret_cast<const float2*>(&Ws[kk][g * 32 + tx * 2]);
                w[g][0] = wv.x;
                w[g][1] = wv.y;
            }
#pragma unroll
            for (int i = 0; i < 8; i++)
#pragma unroll
                for (int g = 0; g < 4; g++) {
                    acc[i][g][0] = fmaf(a[i], w[g][0], acc[i][g][0]);
                    acc[i][g][1] = fmaf(a[i], w[g][1], acc[i][g][1]);
                }
        }
    }
}

// ============================================================================
// Fused GEMM + LSTM-cell stage kernel
// grid = (NROWS/128, 128/32) = (512, 4), block = 256
// ============================================================================
template <int STAGE>
__global__ void __launch_bounds__(256, 2)
lstm_stage_kernel(const float* __restrict__ X) {
    __shared__ float As[32][129];
    __shared__ float Ws[32][128];

    const int tid  = threadIdx.x;
    const int tx   = tid & 15;
    const int ty   = tid >> 4;
    const int row0 = blockIdx.x * 128;
    const int j0   = blockIdx.y * 32;
    const int jc   = j0 + tx * 2;

    float acc[8][4][2];
    {
        const float* initp;
        if (STAGE == 2)      initp = d_mug + (row0 >> 10) * 512;  // per-batch mu gates (incl. bias0)
        else if (STAGE == 1) initp = d_bias0;
        else                 initp = d_bias1;
#pragma unroll
        for (int g = 0; g < 4; g++) {
            float2 bv = *reinterpret_cast<const float2*>(initp + g * 128 + jc);
#pragma unroll
            for (int i = 0; i < 8; i++) {
                acc[i][g][0] = bv.x;
                acc[i][g][1] = bv.y;
            }
        }
    }

    if (STAGE == 1) gemm_source<64>(X,     d_WT0i, row0, j0, tx, ty, tid, acc, As, Ws);
    if (STAGE == 2) gemm_source<128>(d_h1, d_WT0h, row0, j0, tx, ty, tid, acc, As, Ws);
    if (STAGE == 3) gemm_source<128>(d_h1, d_WT1i, row0, j0, tx, ty, tid, acc, As, Ws);
    if (STAGE == 4) {
        gemm_source<128>(d_h2,  d_WT1i, row0, j0, tx, ty, tid, acc, As, Ws);
        gemm_source<128>(d_h1p, d_WT1h, row0, j0, tx, ty, tid, acc, As, Ws);
    }

    // ---- LSTM cell epilogue (gates i,f,g,o are thread-local) ----
#pragma unroll
    for (int i = 0; i < 8; i++) {
        int row = row0 + ty * 8 + i;
        size_t base = (size_t)row * HDIM + jc;

        float cp[2] = {0.0f, 0.0f};
        if (STAGE == 2) {
            float2 v = *reinterpret_cast<const float2*>(d_c1 + base);
            cp[0] = v.x; cp[1] = v.y;
        }
        if (STAGE == 4) {
            float2 v = *reinterpret_cast<const float2*>(d_c1p + base);
            cp[0] = v.x; cp[1] = v.y;
        }

        float hv[2], cv[2];
#pragma unroll
        for (int jj = 0; jj < 2; jj++) {
            float gi = acc[i][0][jj];
            float gf = acc[i][1][jj];
            float gG = acc[i][2][jj];
            float go = acc[i][3][jj];
            float cn;
            if (STAGE == 1 || STAGE == 3)
                cn = sigm_f(gi) * tanh_f(gG);                       // c_prev = 0
            else
                cn = sigm_f(gf) * cp[jj] + sigm_f(gi) * tanh_f(gG);
            float hn = sigm_f(go) * tanh_f(cn);
            if (STAGE == 4) hn = fmaxf(hn, 0.0f);                   // fused ReLU
            hv[jj] = hn;
            cv[jj] = cn;
        }

        float2 hv2 = make_float2(hv[0], hv[1]);
        float2 cv2 = make_float2(cv[0], cv[1]);
        if (STAGE == 1) {
            *reinterpret_cast<float2*>(d_h1 + base) = hv2;
            *reinterpret_cast<float2*>(d_c1 + base) = cv2;
        } else if (STAGE == 2) {
            *reinterpret_cast<float2*>(d_h2 + base) = hv2;
        } else if (STAGE == 3) {
            *reinterpret_cast<float2*>(d_h1p + base) = hv2;
            *reinterpret_cast<float2*>(d_c1p + base) = cv2;
        } else {
            *reinterpret_cast<float2*>(d_h2p + base) = hv2;
        }
    }
}

// ============================================================================
// Final FC: out[n] = relu(h2p[n]) . fc_w + fc_b   (one warp per row)
// ============================================================================
__global__ void fc_kernel(const float* __restrict__ fcw,
                          const float* __restrict__ fcb,
                          float* __restrict__ out) {
    int gtid = blockIdx.x * blockDim.x + threadIdx.x;
    int row  = gtid >> 5;
    int lane = threadIdx.x & 31;
    const float* hr = d_h2p + (size_t)row * HDIM;
    float s = 0.0f;
#pragma unroll
    for (int m = 0; m < 4; m++) {
        int c = lane + 32 * m;
        s = fmaf(hr[c], __ldg(fcw + c), s);
    }
#pragma unroll
    for (int off = 16; off > 0; off >>= 1)
        s += __shfl_down_sync(0xffffffffu, s, off);
    if (lane == 0) out[row] = s + __ldg(fcb);
}

// ============================================================================
// Launch
// ============================================================================
extern "C" void kernel_launch(void* const* d_in, const int* in_sizes, int n_in,
                              void* d_out, int out_size) {
    const float* x    = (const float*)d_in[0];
    const float* mu   = (const float*)d_in[1];
    const float* Wih0 = (const float*)d_in[2];
    const float* Whh0 = (const float*)d_in[3];
    const float* bih0 = (const float*)d_in[4];
    const float* bhh0 = (const float*)d_in[5];
    const float* Wih1 = (const float*)d_in[6];
    const float* Whh1 = (const float*)d_in[7];
    const float* bih1 = (const float*)d_in[8];
    const float* bhh1 = (const float*)d_in[9];
    const float* fcw  = (const float*)d_in[10];
    const float* fcb  = (const float*)d_in[11];
    float* out = (float*)d_out;

    prep_transpose<<<256, 256>>>(Wih0, Whh0, Wih1, Whh1, bih0, bhh0, bih1, bhh1);
    prep_mug<<<64, 512>>>(mu, Wih0);

    dim3 grid(NROWS / 128, HDIM / 32);
    lstm_stage_kernel<1><<<grid, 256>>>(x);
    lstm_stage_kernel<2><<<grid, 256>>>(nullptr);
    lstm_stage_kernel<3><<<grid, 256>>>(nullptr);
    lstm_stage_kernel<4><<<grid, 256>>>(nullptr);

    fc_kernel<<<NROWS / 8, 256>>>(fcw, fcb, out);
}

// round 4
// speedup vs baseline: 1.5133x; 1.5133x over previous
#include <cuda_runtime.h>
#include <cuda_bf16.h>
#include <cstdint>

// ============================================================================
// Forecaster via warp-level bf16 mma.sync (HMMA) + 3xBF16 hi/lo split.
// (tcgen05 PTX does not compile on this harness's sm_103 target.)
//
// Gate-interleaved column packing: unit j's 4 gates live in one thread's
// D fragments -> thread-local LSTM cell epilogue.
// Stage 1: x  @ W0i'  (K=64)   + bias0 -> h1, c1
// Stage 2: h1 @ W0h'  (K=128)  + mug[b] -> h2 (c1)
// Stage 3: h1 @ W1i'  (K=128)  + bias1 -> h1p, c1p
// Stage 4: [h2|h1p] @ [W1i'|W1h'] (K=256) + bias1 -> relu -> FC partials
// ============================================================================

#define NROWS 65536

// ---------------- device scratch (allocation-free) ----------------
__device__ __nv_bfloat16 d_W0i_hi[512 * 64],  d_W0i_lo[512 * 64];
__device__ __nv_bfloat16 d_W0h_hi[512 * 128], d_W0h_lo[512 * 128];
__device__ __nv_bfloat16 d_W1i_hi[512 * 128], d_W1i_lo[512 * 128];
__device__ __nv_bfloat16 d_W1h_hi[512 * 128], d_W1h_lo[512 * 128];
__device__ float d_bias0p[512], d_bias1p[512];
__device__ float d_mug[64 * 512];
__device__ float d_fcw[128];
__device__ float d_fcb_v;

__device__ float d_h1[NROWS * 128];
__device__ float d_h2[NROWS * 128];
__device__ float d_h1p[NROWS * 128];
__device__ float d_c1[NROWS * 128];
__device__ float d_c1p[NROWS * 128];
__device__ float d_fcpart[8 * NROWS];

// ---------------- helpers ----------------
__device__ __forceinline__ uint32_t smem_u32(const void* p) {
    uint32_t a;
    asm("{ .reg .u64 t; cvta.to.shared.u64 t, %1; cvt.u32.u64 %0, t; }"
        : "=r"(a) : "l"(p));
    return a;
}
__device__ __forceinline__ void ldsm4(uint32_t* r, uint32_t a) {
    asm volatile("ldmatrix.sync.aligned.m8n8.x4.shared.b16 {%0,%1,%2,%3}, [%4];"
                 : "=r"(r[0]), "=r"(r[1]), "=r"(r[2]), "=r"(r[3]) : "r"(a));
}
__device__ __forceinline__ void mma16816(float* d, const uint32_t* a, const uint32_t* b) {
    asm volatile(
        "mma.sync.aligned.m16n8k16.row.col.f32.bf16.bf16.f32 "
        "{%0,%1,%2,%3}, {%4,%5,%6,%7}, {%8,%9}, {%0,%1,%2,%3};"
        : "+f"(d[0]), "+f"(d[1]), "+f"(d[2]), "+f"(d[3])
        : "r"(a[0]), "r"(a[1]), "r"(a[2]), "r"(a[3]), "r"(b[0]), "r"(b[1]));
}
__device__ __forceinline__ float sigm_f(float x) {
    return __fdividef(1.0f, 1.0f + __expf(-x));
}
__device__ __forceinline__ float tanh_f(float x) {
    return __fdividef(2.0f, 1.0f + __expf(-2.0f * x)) - 1.0f;
}

// packed-column mapping: c' -> (gate, unit j). Gates order (i,f,g,o).
__device__ __forceinline__ void cmap(int c_, int& gate, int& j) {
    int chunk = c_ >> 7, r = c_ & 127, cg = (r >> 6) & 1, s = r & 63;
    int t = s >> 3, c = s & 7, p = t >> 1, th = t & 1, q = c >> 1, par = c & 1;
    gate = th * 2 + par;
    j = (chunk << 5) + (cg << 4) + (p << 2) + q;
}

// ============================================================================
// Prep: pack+split weights, biases, mug, fc
// ============================================================================
__device__ __forceinline__ void wsplit(float w, __nv_bfloat16* hi, __nv_bfloat16* lo, int i) {
    __nv_bfloat16 h = __float2bfloat16(w);
    hi[i] = h;
    lo[i] = __float2bfloat16(w - __bfloat162float(h));
}

__global__ void prep_pack(const float* __restrict__ Wih0, const float* __restrict__ Whh0,
                          const float* __restrict__ Wih1, const float* __restrict__ Whh1,
                          const float* __restrict__ bih0, const float* __restrict__ bhh0,
                          const float* __restrict__ bih1, const float* __restrict__ bhh1,
                          const float* __restrict__ fcw, const float* __restrict__ fcb) {
    int i = blockIdx.x * 256 + threadIdx.x;    // 65536 threads
    int c_ = i >> 7, k = i & 127;
    int gate, j;
    cmap(c_, gate, j);
    int G = gate * 128 + j;
    wsplit(Whh0[G * 128 + k], d_W0h_hi, d_W0h_lo, c_ * 128 + k);
    wsplit(Wih1[G * 128 + k], d_W1i_hi, d_W1i_lo, c_ * 128 + k);
    wsplit(Whh1[G * 128 + k], d_W1h_hi, d_W1h_lo, c_ * 128 + k);
    if (k < 64) wsplit(Wih0[G * 64 + k], d_W0i_hi, d_W0i_lo, c_ * 64 + k);
    if (k == 0) {
        d_bias0p[c_] = bih0[G] + bhh0[G];
        d_bias1p[c_] = bih1[G] + bhh1[G];
    }
    if (i < 128) d_fcw[i] = fcw[i];
    if (i == 0) d_fcb_v = fcb[0];
}

__global__ void prep_mug(const float* __restrict__ mu,
                         const float* __restrict__ Wih0,
                         const float* __restrict__ bih0,
                         const float* __restrict__ bhh0) {
    __shared__ float mur[64];
    int c_ = threadIdx.x;
    if (c_ < 64) mur[c_] = mu[blockIdx.x * 64 + c_];
    __syncthreads();
    int gate, j;
    cmap(c_, gate, j);
    int G = gate * 128 + j;
    float s = bih0[G] + bhh0[G];
    const float* wr = Wih0 + G * 64;
#pragma unroll
    for (int k = 0; k < 64; k++) s = fmaf(mur[k], wr[k], s);
    d_mug[blockIdx.x * 512 + c_] = s;
}

// ============================================================================
// SMEM fills (padded stride = 2*KT+16 bytes -> conflict-free ldmatrix)
// ============================================================================
template <int KT>
__device__ __forceinline__ void fillA_split(uint32_t sAh, uint32_t sAl,
                                            const float* __restrict__ g,
                                            int row0, int tid) {
    constexpr int ST = KT * 2 + 16;
    constexpr int F4R = KT / 4;
#pragma unroll
    for (int it = 0; it < 128 * F4R / 256; it++) {
        int e = tid + it * 256;
        int row = e / F4R;
        int kq = (e % F4R) * 4;
        float4 v = *reinterpret_cast<const float4*>(g + (size_t)(row0 + row) * KT + kq);
        __nv_bfloat162 h01 = __floats2bfloat162_rn(v.x, v.y);
        __nv_bfloat162 h23 = __floats2bfloat162_rn(v.z, v.w);
        float l0 = v.x - __bfloat162float(h01.x);
        float l1 = v.y - __bfloat162float(h01.y);
        float l2 = v.z - __bfloat162float(h23.x);
        float l3 = v.w - __bfloat162float(h23.y);
        __nv_bfloat162 q01 = __floats2bfloat162_rn(l0, l1);
        __nv_bfloat162 q23 = __floats2bfloat162_rn(l2, l3);
        uint32_t byte = (uint32_t)row * ST + kq * 2;
        uint32_t uh0 = *reinterpret_cast<uint32_t*>(&h01);
        uint32_t uh1 = *reinterpret_cast<uint32_t*>(&h23);
        uint32_t ul0 = *reinterpret_cast<uint32_t*>(&q01);
        uint32_t ul1 = *reinterpret_cast<uint32_t*>(&q23);
        asm volatile("st.shared.v2.b32 [%0], {%1,%2};" :: "r"(sAh + byte), "r"(uh0), "r"(uh1));
        asm volatile("st.shared.v2.b32 [%0], {%1,%2};" :: "r"(sAl + byte), "r"(ul0), "r"(ul1));
    }
}

template <int KT>
__device__ __forceinline__ void fillB(uint32_t sB, const __nv_bfloat16* __restrict__ g,
                                      int c0, int tid) {
    constexpr int ST = KT * 2 + 16;
    constexpr int C8R = KT / 8;
#pragma unroll
    for (int it = 0; it < 128 * C8R / 256; it++) {
        int e = tid + it * 256;
        int row = e / C8R;
        int kq = (e % C8R) * 8;
        uint4 v = *reinterpret_cast<const uint4*>(g + (size_t)(c0 + row) * KT + kq);
        uint32_t byte = (uint32_t)row * ST + kq * 2;
        asm volatile("st.shared.v4.b32 [%0], {%1,%2,%3,%4};"
                     :: "r"(sB + byte), "r"(v.x), "r"(v.y), "r"(v.z), "r"(v.w));
    }
}

// ============================================================================
// MMA sweep: warp tile 32 rows x 64 cols, acc[2][8][4]
// ============================================================================
template <int KT>
__device__ __forceinline__ void sweep(uint32_t sA, uint32_t sB, int lane,
                                      int m0, int n0, float (&acc)[2][8][4]) {
    constexpr int ST = KT * 2 + 16;
    const uint32_t lrow = (uint32_t)(lane & 15);
    const uint32_t lhi = (uint32_t)(lane >> 4) * 16u;
    const uint32_t aBase0 = sA + (m0 + lrow) * ST + lhi;
    const uint32_t aBase1 = aBase0 + 16 * ST;
    const uint32_t bBase = sB + (n0 + lrow) * ST + lhi;
#pragma unroll
    for (int kc = 0; kc < KT / 16; kc++) {
        const uint32_t ko = kc * 32;
        uint32_t a0[4], a1[4], b[4][4];
        ldsm4(a0, aBase0 + ko);
        ldsm4(a1, aBase1 + ko);
#pragma unroll
        for (int pr = 0; pr < 4; pr++) ldsm4(b[pr], bBase + pr * 16 * ST + ko);
#pragma unroll
        for (int pr = 0; pr < 4; pr++) {
            uint32_t be[2] = {b[pr][0], b[pr][2]};
            uint32_t bo[2] = {b[pr][1], b[pr][3]};
            mma16816(acc[0][2 * pr], a0, be);
            mma16816(acc[1][2 * pr], a1, be);
            mma16816(acc[0][2 * pr + 1], a0, bo);
            mma16816(acc[1][2 * pr + 1], a1, bo);
        }
    }
}

// ============================================================================
// Stage kernel: grid (512, 4), 256 threads, CTA = 128 rows x 128 packed cols
// ============================================================================
template <int STAGE>
__global__ void __launch_bounds__(256)
lstm_stage(const float* __restrict__ Ax) {
    extern __shared__ __align__(128) char dsm[];
    __shared__ float s_add[128];

    constexpr int KT = (STAGE == 1) ? 64 : 128;
    constexpr int ST = KT * 2 + 16;
    constexpr int TILE = 128 * ST;

    const int tid = threadIdx.x;
    const int lane = tid & 31;
    const int wid = tid >> 5;
    const int rg = wid >> 1;          // row group 0..3 (32 rows each)
    const int cg = wid & 1;           // col group 0..1 (64 cols each)
    const int row0 = blockIdx.x * 128;
    const int chunk = blockIdx.y;

    const uint32_t s0 = smem_u32(dsm);
    const uint32_t sAh = s0, sAl = s0 + TILE, sBh = s0 + 2 * TILE, sBl = s0 + 3 * TILE;

    if (tid < 128) {
        const float* src = (STAGE == 1) ? d_bias0p
                         : (STAGE == 2) ? (d_mug + (blockIdx.x >> 3) * 512)
                                        : d_bias1p;
        s_add[tid] = src[chunk * 128 + tid];
    }

    float acc[2][8][4];
#pragma unroll
    for (int a = 0; a < 2; a++)
#pragma unroll
        for (int b = 0; b < 8; b++)
#pragma unroll
            for (int c = 0; c < 4; c++) acc[a][b][c] = 0.0f;

    const int m0 = rg * 32;
    const int n0 = cg * 64;

    if (STAGE != 4) {
        const float* A = (STAGE == 1) ? Ax : d_h1;
        fillA_split<KT>(sAh, sAl, A, row0, tid);
        const __nv_bfloat16* BH;
        const __nv_bfloat16* BL;
        if (STAGE == 1)      { BH = d_W0i_hi; BL = d_W0i_lo; }
        else if (STAGE == 2) { BH = d_W0h_hi; BL = d_W0h_lo; }
        else                 { BH = d_W1i_hi; BL = d_W1i_lo; }
        fillB<KT>(sBh, BH, chunk * 128, tid);
        fillB<KT>(sBl, BL, chunk * 128, tid);
        __syncthreads();
        sweep<KT>(sAh, sBh, lane, m0, n0, acc);
        sweep<KT>(sAh, sBl, lane, m0, n0, acc);
        sweep<KT>(sAl, sBh, lane, m0, n0, acc);
    } else {
        // phase 0: h2 @ W1i'
        fillA_split<128>(sAh, sAl, d_h2, row0, tid);
        fillB<128>(sBh, d_W1i_hi, chunk * 128, tid);
        fillB<128>(sBl, d_W1i_lo, chunk * 128, tid);
        __syncthreads();
        sweep<128>(sAh, sBh, lane, m0, n0, acc);
        sweep<128>(sAh, sBl, lane, m0, n0, acc);
        sweep<128>(sAl, sBh, lane, m0, n0, acc);
        __syncthreads();
        // phase 1: h1p @ W1h'
        fillA_split<128>(sAh, sAl, d_h1p, row0, tid);
        fillB<128>(sBh, d_W1h_hi, chunk * 128, tid);
        fillB<128>(sBl, d_W1h_lo, chunk * 128, tid);
        __syncthreads();
        sweep<128>(sAh, sBh, lane, m0, n0, acc);
        sweep<128>(sAh, sBl, lane, m0, n0, acc);
        sweep<128>(sAl, sBh, lane, m0, n0, acc);
    }

    // ---- thread-local LSTM cell epilogue ----
    const int q = lane & 3;
    const int Jcg = chunk * 32 + cg * 16;
    float fc[4] = {0.0f, 0.0f, 0.0f, 0.0f};

#pragma unroll
    for (int mt = 0; mt < 2; mt++) {
#pragma unroll
        for (int p = 0; p < 4; p++) {
            const int aidx = cg * 64 + p * 16 + q * 2;
            const float addi = s_add[aidx];
            const float addf = s_add[aidx + 1];
            const float addg = s_add[aidx + 8];
            const float addo = s_add[aidx + 9];
            const int j = Jcg + p * 4 + q;
#pragma unroll
            for (int h2 = 0; h2 < 2; h2++) {
                const int row = row0 + rg * 32 + mt * 16 + (lane >> 2) + h2 * 8;
                const size_t idx = (size_t)row * 128 + j;
                float gi = acc[mt][2 * p][h2 * 2 + 0] + addi;
                float gf = acc[mt][2 * p][h2 * 2 + 1] + addf;
                float gg = acc[mt][2 * p + 1][h2 * 2 + 0] + addg;
                float go = acc[mt][2 * p + 1][h2 * 2 + 1] + addo;
                float cn;
                if (STAGE == 1 || STAGE == 3) {
                    cn = sigm_f(gi) * tanh_f(gg);
                } else {
                    const float cp = (STAGE == 2) ? d_c1[idx] : d_c1p[idx];
                    cn = sigm_f(gf) * cp + sigm_f(gi) * tanh_f(gg);
                }
                float hn = sigm_f(go) * tanh_f(cn);
                if (STAGE == 1) { d_h1[idx] = hn; d_c1[idx] = cn; }
                if (STAGE == 2) { d_h2[idx] = hn; }
                if (STAGE == 3) { d_h1p[idx] = hn; d_c1p[idx] = cn; }
                if (STAGE == 4) {
                    fc[mt * 2 + h2] = fmaf(fmaxf(hn, 0.0f), d_fcw[j], fc[mt * 2 + h2]);
                }
            }
        }
    }

    if (STAGE == 4) {
#pragma unroll
        for (int s = 0; s < 4; s++) {
            float v = fc[s];
            v += __shfl_xor_sync(0xffffffffu, v, 1);
            v += __shfl_xor_sync(0xffffffffu, v, 2);
            if (q == 0) {
                const int row = row0 + rg * 32 + (s >> 1) * 16 + (lane >> 2) + (s & 1) * 8;
                d_fcpart[(chunk * 2 + cg) * NROWS + row] = v;
            }
        }
    }
}

// ============================================================================
// FC reduce: out[r] = fcb + sum of 8 partials (deterministic)
// ============================================================================
__global__ void fc_reduce(float* __restrict__ out) {
    int r = blockIdx.x * 256 + threadIdx.x;
    float s = d_fcb_v;
#pragma unroll
    for (int i = 0; i < 8; i++) s += d_fcpart[i * NROWS + r];
    out[r] = s;
}

// ============================================================================
// Launch
// ============================================================================
extern "C" void kernel_launch(void* const* d_in, const int* in_sizes, int n_in,
                              void* d_out, int out_size) {
    const float* x    = (const float*)d_in[0];
    const float* mu   = (const float*)d_in[1];
    const float* Wih0 = (const float*)d_in[2];
    const float* Whh0 = (const float*)d_in[3];
    const float* bih0 = (const float*)d_in[4];
    const float* bhh0 = (const float*)d_in[5];
    const float* Wih1 = (const float*)d_in[6];
    const float* Whh1 = (const float*)d_in[7];
    const float* bih1 = (const float*)d_in[8];
    const float* bhh1 = (const float*)d_in[9];
    const float* fcw  = (const float*)d_in[10];
    const float* fcb  = (const float*)d_in[11];
    float* out = (float*)d_out;

    const int S1 = 4 * 128 * (64 * 2 + 16);    //  73728
    const int S2 = 4 * 128 * (128 * 2 + 16);   // 139264
    cudaFuncSetAttribute(lstm_stage<1>, cudaFuncAttributeMaxDynamicSharedMemorySize, S1);
    cudaFuncSetAttribute(lstm_stage<2>, cudaFuncAttributeMaxDynamicSharedMemorySize, S2);
    cudaFuncSetAttribute(lstm_stage<3>, cudaFuncAttributeMaxDynamicSharedMemorySize, S2);
    cudaFuncSetAttribute(lstm_stage<4>, cudaFuncAttributeMaxDynamicSharedMemorySize, S2);

    prep_pack<<<256, 256>>>(Wih0, Whh0, Wih1, Whh1, bih0, bhh0, bih1, bhh1, fcw, fcb);
    prep_mug<<<64, 512>>>(mu, Wih0, bih0, bhh0);

    dim3 grid(512, 4);
    lstm_stage<1><<<grid, 256, S1>>>(x);
    lstm_stage<2><<<grid, 256, S2>>>(nullptr);
    lstm_stage<3><<<grid, 256, S2>>>(nullptr);
    lstm_stage<4><<<grid, 256, S2>>>(nullptr);

    fc_reduce<<<256, 256>>>(out);
}

// round 6
// speedup vs baseline: 1.5784x; 1.0430x over previous
#include <cuda_runtime.h>
#include <cuda_bf16.h>
#include <cstdint>

// ============================================================================
// Forecaster via warp mma.sync bf16 + 3x hi/lo split, v2:
//  - 512 threads/CTA (16 warps, 32x32 warp tiles) -> 4 warps/SMSP
//  - activations stored pre-split bf16 hi/lo -> cp.async fills, staged groups
//  - stages 2+3 merged (both read h1); stage 4 keeps both A tiles resident
// ============================================================================

#define NROWS 65536

// ---------------- device scratch (allocation-free, 16B aligned for cp.async) ----
__device__ __align__(16) __nv_bfloat16 d_W0i_hi[512 * 64],  d_W0i_lo[512 * 64];
__device__ __align__(16) __nv_bfloat16 d_W0h_hi[512 * 128], d_W0h_lo[512 * 128];
__device__ __align__(16) __nv_bfloat16 d_W1i_hi[512 * 128], d_W1i_lo[512 * 128];
__device__ __align__(16) __nv_bfloat16 d_W1h_hi[512 * 128], d_W1h_lo[512 * 128];
__device__ float d_bias0p[512], d_bias1p[512];
__device__ float d_mug[64 * 512];
__device__ float d_fcw[128];
__device__ float d_fcb_v;

__device__ __align__(16) __nv_bfloat16 d_x_hi[NROWS * 64],   d_x_lo[NROWS * 64];
__device__ __align__(16) __nv_bfloat16 d_h1_hi[NROWS * 128], d_h1_lo[NROWS * 128];
__device__ __align__(16) __nv_bfloat16 d_h2_hi[NROWS * 128], d_h2_lo[NROWS * 128];
__device__ __align__(16) __nv_bfloat16 d_h1p_hi[NROWS * 128], d_h1p_lo[NROWS * 128];
__device__ float d_c1[NROWS * 128];
__device__ float d_c1p[NROWS * 128];
__device__ float d_fcpart[16 * NROWS];

// ---------------- helpers ----------------
__device__ __forceinline__ uint32_t smem_u32(const void* p) {
    uint32_t a;
    asm("{ .reg .u64 t; cvta.to.shared.u64 t, %1; cvt.u32.u64 %0, t; }"
        : "=r"(a) : "l"(p));
    return a;
}
__device__ __forceinline__ void ldsm4(uint32_t* r, uint32_t a) {
    asm volatile("ldmatrix.sync.aligned.m8n8.x4.shared.b16 {%0,%1,%2,%3}, [%4];"
                 : "=r"(r[0]), "=r"(r[1]), "=r"(r[2]), "=r"(r[3]) : "r"(a));
}
__device__ __forceinline__ void mma16816(float* d, const uint32_t* a, const uint32_t* b) {
    asm volatile(
        "mma.sync.aligned.m16n8k16.row.col.f32.bf16.bf16.f32 "
        "{%0,%1,%2,%3}, {%4,%5,%6,%7}, {%8,%9}, {%0,%1,%2,%3};"
        : "+f"(d[0]), "+f"(d[1]), "+f"(d[2]), "+f"(d[3])
        : "r"(a[0]), "r"(a[1]), "r"(a[2]), "r"(a[3]), "r"(b[0]), "r"(b[1]));
}
#define CP_COMMIT() asm volatile("cp.async.commit_group;" ::: "memory")
#define CP_WAIT(n)  asm volatile("cp.async.wait_group %0;" :: "n"(n) : "memory")

__device__ __forceinline__ float sigm_f(float x) {
    return __fdividef(1.0f, 1.0f + __expf(-x));
}
__device__ __forceinline__ float tanh_f(float x) {
    return __fdividef(2.0f, 1.0f + __expf(-2.0f * x)) - 1.0f;
}

// packed-column mapping: c' -> (gate, unit j). Gates order (i,f,g,o).
__device__ __forceinline__ void cmap(int c_, int& gate, int& j) {
    int chunk = c_ >> 7, r = c_ & 127, cg = (r >> 6) & 1, s = r & 63;
    int t = s >> 3, c = s & 7, p = t >> 1, th = t & 1, q = c >> 1, par = c & 1;
    gate = th * 2 + par;
    j = (chunk << 5) + (cg << 4) + (p << 2) + q;
}

// ============================================================================
// Prep kernels
// ============================================================================
__device__ __forceinline__ void wsplit(float w, __nv_bfloat16* hi, __nv_bfloat16* lo, int i) {
    __nv_bfloat16 h = __float2bfloat16(w);
    hi[i] = h;
    lo[i] = __float2bfloat16(w - __bfloat162float(h));
}

__global__ void prep_pack(const float* __restrict__ Wih0, const float* __restrict__ Whh0,
                          const float* __restrict__ Wih1, const float* __restrict__ Whh1,
                          const float* __restrict__ bih0, const float* __restrict__ bhh0,
                          const float* __restrict__ bih1, const float* __restrict__ bhh1,
                          const float* __restrict__ fcw, const float* __restrict__ fcb) {
    int i = blockIdx.x * 256 + threadIdx.x;    // 65536 threads
    int c_ = i >> 7, k = i & 127;
    int gate, j;
    cmap(c_, gate, j);
    int G = gate * 128 + j;
    wsplit(Whh0[G * 128 + k], d_W0h_hi, d_W0h_lo, c_ * 128 + k);
    wsplit(Wih1[G * 128 + k], d_W1i_hi, d_W1i_lo, c_ * 128 + k);
    wsplit(Whh1[G * 128 + k], d_W1h_hi, d_W1h_lo, c_ * 128 + k);
    if (k < 64) wsplit(Wih0[G * 64 + k], d_W0i_hi, d_W0i_lo, c_ * 64 + k);
    if (k == 0) {
        d_bias0p[c_] = bih0[G] + bhh0[G];
        d_bias1p[c_] = bih1[G] + bhh1[G];
    }
    if (i < 128) d_fcw[i] = fcw[i];
    if (i == 0) d_fcb_v = fcb[0];
}

__global__ void prep_mug(const float* __restrict__ mu,
                         const float* __restrict__ Wih0,
                         const float* __restrict__ bih0,
                         const float* __restrict__ bhh0) {
    __shared__ float mur[64];
    int c_ = threadIdx.x;
    if (c_ < 64) mur[c_] = mu[blockIdx.x * 64 + c_];
    __syncthreads();
    int gate, j;
    cmap(c_, gate, j);
    int G = gate * 128 + j;
    float s = bih0[G] + bhh0[G];
    const float* wr = Wih0 + G * 64;
#pragma unroll
    for (int k = 0; k < 64; k++) s = fmaf(mur[k], wr[k], s);
    d_mug[blockIdx.x * 512 + c_] = s;
}

__global__ void prep_x(const float* __restrict__ x) {
    int i = blockIdx.x * 256 + threadIdx.x;      // x4 elems each
    float4 v = reinterpret_cast<const float4*>(x)[i];
    __nv_bfloat162 h01 = __floats2bfloat162_rn(v.x, v.y);
    __nv_bfloat162 h23 = __floats2bfloat162_rn(v.z, v.w);
    __nv_bfloat162 l01 = __floats2bfloat162_rn(v.x - __bfloat162float(h01.x),
                                               v.y - __bfloat162float(h01.y));
    __nv_bfloat162 l23 = __floats2bfloat162_rn(v.z - __bfloat162float(h23.x),
                                               v.w - __bfloat162float(h23.y));
    reinterpret_cast<uint2*>(d_x_hi)[i] =
        make_uint2(*reinterpret_cast<uint32_t*>(&h01), *reinterpret_cast<uint32_t*>(&h23));
    reinterpret_cast<uint2*>(d_x_lo)[i] =
        make_uint2(*reinterpret_cast<uint32_t*>(&l01), *reinterpret_cast<uint32_t*>(&l23));
}

// ============================================================================
// cp.async SMEM fill: 128 rows x KT bf16, padded stride ST = 2*KT+16 bytes
// ============================================================================
template <int KT>
__device__ __forceinline__ void cp_fill(uint32_t sdst, const __nv_bfloat16* __restrict__ g,
                                        int row0, int tid) {
    constexpr int ST = KT * 2 + 16;
    constexpr int CPR = KT / 8;                  // 16B chunks per row
    constexpr int ITER = 128 * CPR / 512;
#pragma unroll
    for (int t = 0; t < ITER; t++) {
        int e = tid + t * 512;
        int row = e / CPR;
        int kq = (e % CPR) * 8;
        uint32_t d = sdst + (uint32_t)row * ST + (uint32_t)kq * 2;
        const void* s = g + (size_t)(row0 + row) * KT + kq;
        asm volatile("cp.async.cg.shared.global [%0], [%1], 16;" :: "r"(d), "l"(s));
    }
}

// ============================================================================
// MMA sweep: warp tile 32 rows x 32 cols, acc[2][4][4]
// ============================================================================
template <int KT>
__device__ __forceinline__ void sweep(uint32_t sA, uint32_t sB, int lane,
                                      int m0, int n0, float (&acc)[2][4][4]) {
    constexpr int ST = KT * 2 + 16;
    const uint32_t lrow = (uint32_t)(lane & 15);
    const uint32_t lhi = (uint32_t)(lane >> 4) * 16u;
    const uint32_t aB0 = sA + (m0 + lrow) * ST + lhi;
    const uint32_t aB1 = aB0 + 16 * ST;
    const uint32_t bB0 = sB + (n0 + lrow) * ST + lhi;
    const uint32_t bB1 = bB0 + 16 * ST;
#pragma unroll
    for (int kc = 0; kc < KT / 16; kc++) {
        const uint32_t ko = kc * 32;
        uint32_t a0[4], a1[4], b0[4], b1[4];
        ldsm4(a0, aB0 + ko);
        ldsm4(a1, aB1 + ko);
        ldsm4(b0, bB0 + ko);
        ldsm4(b1, bB1 + ko);
        uint32_t be0[2] = {b0[0], b0[2]}, bo0[2] = {b0[1], b0[3]};
        uint32_t be1[2] = {b1[0], b1[2]}, bo1[2] = {b1[1], b1[3]};
        mma16816(acc[0][0], a0, be0); mma16816(acc[1][0], a1, be0);
        mma16816(acc[0][1], a0, bo0); mma16816(acc[1][1], a1, bo0);
        mma16816(acc[0][2], a0, be1); mma16816(acc[1][2], a1, be1);
        mma16816(acc[0][3], a0, bo1); mma16816(acc[1][3], a1, bo1);
    }
}

// ============================================================================
// Epilogue (thread-local LSTM cell; MODE 1:h1/c1  2:h2(c1)  3:h1p/c1p  4:fc(c1p))
// ============================================================================
template <int MODE>
__device__ __forceinline__ void epilogue(const float (&acc)[2][4][4],
                                         const float* s_add, const float* s_fcw,
                                         int row0, int chunk, int rg, int cg, int lane) {
    const int q = lane & 3;
    float fc[4] = {0.0f, 0.0f, 0.0f, 0.0f};
#pragma unroll
    for (int mt = 0; mt < 2; mt++) {
#pragma unroll
        for (int pr = 0; pr < 2; pr++) {
            const int aidx = cg * 32 + pr * 16 + q * 2;
            const float addi = s_add[aidx];
            const float addf = s_add[aidx + 1];
            const float addg = s_add[aidx + 8];
            const float addo = s_add[aidx + 9];
            const int j = chunk * 32 + (cg * 2 + pr) * 4 + q;
#pragma unroll
            for (int h2 = 0; h2 < 2; h2++) {
                const int row = row0 + rg * 32 + mt * 16 + (lane >> 2) + h2 * 8;
                const size_t idx = (size_t)row * 128 + j;
                float gi = acc[mt][2 * pr][h2 * 2 + 0] + addi;
                float gf = acc[mt][2 * pr][h2 * 2 + 1] + addf;
                float gg = acc[mt][2 * pr + 1][h2 * 2 + 0] + addg;
                float go = acc[mt][2 * pr + 1][h2 * 2 + 1] + addo;
                float cn;
                if (MODE == 1 || MODE == 3) {
                    cn = sigm_f(gi) * tanh_f(gg);
                } else {
                    const float cp = (MODE == 2) ? d_c1[idx] : d_c1p[idx];
                    cn = sigm_f(gf) * cp + sigm_f(gi) * tanh_f(gg);
                }
                float hn = sigm_f(go) * tanh_f(cn);
                if (MODE == 4) {
                    fc[mt * 2 + h2] = fmaf(fmaxf(hn, 0.0f), s_fcw[(cg * 2 + pr) * 4 + q],
                                           fc[mt * 2 + h2]);
                } else {
                    __nv_bfloat16 h = __float2bfloat16(hn);
                    __nv_bfloat16 l = __float2bfloat16(hn - __bfloat162float(h));
                    if (MODE == 1) { d_h1_hi[idx] = h;  d_h1_lo[idx] = l;  d_c1[idx] = cn; }
                    if (MODE == 2) { d_h2_hi[idx] = h;  d_h2_lo[idx] = l; }
                    if (MODE == 3) { d_h1p_hi[idx] = h; d_h1p_lo[idx] = l; d_c1p[idx] = cn; }
                }
            }
        }
    }
    if (MODE == 4) {
#pragma unroll
        for (int s = 0; s < 4; s++) {
            float v = fc[s];
            v += __shfl_xor_sync(0xffffffffu, v, 1);
            v += __shfl_xor_sync(0xffffffffu, v, 2);
            if (q == 0) {
                const int row = row0 + rg * 32 + (s >> 1) * 16 + (lane >> 2) + (s & 1) * 8;
                d_fcpart[(chunk * 4 + cg) * NROWS + row] = v;
            }
        }
    }
}

// ============================================================================
// Stage 1: x @ W0i' (K=64) -> h1, c1.   grid (512, 4), 512 threads
// ============================================================================
__global__ void __launch_bounds__(512) lstm_stage1() {
    extern __shared__ __align__(128) char dsm[];
    __shared__ float s_add[128];
    constexpr int KT = 64, ST = KT * 2 + 16, TILE = 128 * ST;

    const int tid = threadIdx.x, lane = tid & 31, wid = tid >> 5;
    const int rg = wid >> 2, cg = wid & 3;
    const int row0 = blockIdx.x * 128, chunk = blockIdx.y;
    const uint32_t s0 = smem_u32(dsm);
    const uint32_t sAh = s0, sAl = s0 + TILE, sBh = s0 + 2 * TILE, sBl = s0 + 3 * TILE;

    if (tid < 128) s_add[tid] = d_bias0p[chunk * 128 + tid];

    cp_fill<KT>(sAh, d_x_hi, row0, tid);
    cp_fill<KT>(sBh, d_W0i_hi + chunk * 128 * KT, 0, tid);
    CP_COMMIT();
    cp_fill<KT>(sBl, d_W0i_lo + chunk * 128 * KT, 0, tid);
    CP_COMMIT();
    cp_fill<KT>(sAl, d_x_lo, row0, tid);
    CP_COMMIT();

    float acc[2][4][4] = {};
    const int m0 = rg * 32, n0 = cg * 32;
    CP_WAIT(2); __syncthreads();
    sweep<KT>(sAh, sBh, lane, m0, n0, acc);
    CP_WAIT(1); __syncthreads();
    sweep<KT>(sAh, sBl, lane, m0, n0, acc);
    CP_WAIT(0); __syncthreads();
    sweep<KT>(sAl, sBh, lane, m0, n0, acc);

    epilogue<1>(acc, s_add, nullptr, row0, chunk, rg, cg, lane);
}

// ============================================================================
// Stages 2+3 merged: grid (512, 8); y<4 -> stage2 (W0h, mug, c1 -> h2),
//                    y>=4 -> stage3 (W1i, bias1 -> h1p, c1p)
// ============================================================================
__global__ void __launch_bounds__(512) lstm_stage23() {
    extern __shared__ __align__(128) char dsm[];
    __shared__ float s_add[128];
    constexpr int KT = 128, ST = KT * 2 + 16, TILE = 128 * ST;

    const int tid = threadIdx.x, lane = tid & 31, wid = tid >> 5;
    const int rg = wid >> 2, cg = wid & 3;
    const int row0 = blockIdx.x * 128;
    const bool is2 = blockIdx.y < 4;
    const int chunk = blockIdx.y & 3;
    const uint32_t s0 = smem_u32(dsm);
    const uint32_t sAh = s0, sAl = s0 + TILE, sBh = s0 + 2 * TILE, sBl = s0 + 3 * TILE;

    if (tid < 128) {
        const float* src = is2 ? (d_mug + (blockIdx.x >> 3) * 512) : d_bias1p;
        s_add[tid] = src[chunk * 128 + tid];
    }
    const __nv_bfloat16* Bh = (is2 ? d_W0h_hi : d_W1i_hi) + chunk * 128 * KT;
    const __nv_bfloat16* Bl = (is2 ? d_W0h_lo : d_W1i_lo) + chunk * 128 * KT;

    cp_fill<KT>(sAh, d_h1_hi, row0, tid);
    cp_fill<KT>(sBh, Bh, 0, tid);
    CP_COMMIT();
    cp_fill<KT>(sBl, Bl, 0, tid);
    CP_COMMIT();
    cp_fill<KT>(sAl, d_h1_lo, row0, tid);
    CP_COMMIT();

    float acc[2][4][4] = {};
    const int m0 = rg * 32, n0 = cg * 32;
    CP_WAIT(2); __syncthreads();
    sweep<KT>(sAh, sBh, lane, m0, n0, acc);
    CP_WAIT(1); __syncthreads();
    sweep<KT>(sAh, sBl, lane, m0, n0, acc);
    CP_WAIT(0); __syncthreads();
    sweep<KT>(sAl, sBh, lane, m0, n0, acc);

    if (is2) epilogue<2>(acc, s_add, nullptr, row0, chunk, rg, cg, lane);
    else     epilogue<3>(acc, s_add, nullptr, row0, chunk, rg, cg, lane);
}

// ============================================================================
// Stage 4: [h2 | h1p] @ [W1i' | W1h'] (K=256) -> relu -> FC partials
// grid (512, 4); both A tiles resident, B refilled once.
// ============================================================================
__global__ void __launch_bounds__(512) lstm_stage4() {
    extern __shared__ __align__(128) char dsm[];
    __shared__ float s_add[128];
    __shared__ float s_fcw[32];
    constexpr int KT = 128, ST = KT * 2 + 16, TILE = 128 * ST;

    const int tid = threadIdx.x, lane = tid & 31, wid = tid >> 5;
    const int rg = wid >> 2, cg = wid & 3;
    const int row0 = blockIdx.x * 128, chunk = blockIdx.y;
    const uint32_t s0 = smem_u32(dsm);
    const uint32_t sA0h = s0, sA0l = s0 + TILE;
    const uint32_t sA1h = s0 + 2 * TILE, sA1l = s0 + 3 * TILE;
    const uint32_t sBh = s0 + 4 * TILE, sBl = s0 + 5 * TILE;

    if (tid < 128) s_add[tid] = d_bias1p[chunk * 128 + tid];
    if (tid < 32)  s_fcw[tid] = d_fcw[chunk * 32 + tid];

    cp_fill<KT>(sA0h, d_h2_hi, row0, tid);
    cp_fill<KT>(sBh, d_W1i_hi + chunk * 128 * KT, 0, tid);
    CP_COMMIT();
    cp_fill<KT>(sBl, d_W1i_lo + chunk * 128 * KT, 0, tid);
    CP_COMMIT();
    cp_fill<KT>(sA0l, d_h2_lo, row0, tid);
    CP_COMMIT();
    cp_fill<KT>(sA1h, d_h1p_hi, row0, tid);
    cp_fill<KT>(sA1l, d_h1p_lo, row0, tid);
    CP_COMMIT();

    float acc[2][4][4] = {};
    const int m0 = rg * 32, n0 = cg * 32;
    CP_WAIT(3); __syncthreads();
    sweep<KT>(sA0h, sBh, lane, m0, n0, acc);
    CP_WAIT(2); __syncthreads();
    sweep<KT>(sA0h, sBl, lane, m0, n0, acc);
    CP_WAIT(1); __syncthreads();
    sweep<KT>(sA0l, sBh, lane, m0, n0, acc);
    CP_WAIT(0); __syncthreads();          // A1 ready; all warps done with B(W1i)

    cp_fill<KT>(sBh, d_W1h_hi + chunk * 128 * KT, 0, tid);
    CP_COMMIT();
    cp_fill<KT>(sBl, d_W1h_lo + chunk * 128 * KT, 0, tid);
    CP_COMMIT();
    CP_WAIT(1); __syncthreads();
    sweep<KT>(sA1h, sBh, lane, m0, n0, acc);
    CP_WAIT(0); __syncthreads();
    sweep<KT>(sA1h, sBl, lane, m0, n0, acc);
    sweep<KT>(sA1l, sBh, lane, m0, n0, acc);

    epilogue<4>(acc, s_add, s_fcw, row0, chunk, rg, cg, lane);
}

// ============================================================================
// FC reduce: out[r] = fcb + sum of 16 partials (deterministic)
// ============================================================================
__global__ void fc_reduce(float* __restrict__ out) {
    int r = blockIdx.x * 256 + threadIdx.x;
    float s = d_fcb_v;
#pragma unroll
    for (int i = 0; i < 16; i++) s += d_fcpart[i * NROWS + r];
    out[r] = s;
}

// ============================================================================
// Launch
// ============================================================================
extern "C" void kernel_launch(void* const* d_in, const int* in_sizes, int n_in,
                              void* d_out, int out_size) {
    const float* x    = (const float*)d_in[0];
    const float* mu   = (const float*)d_in[1];
    const float* Wih0 = (const float*)d_in[2];
    const float* Whh0 = (const float*)d_in[3];
    const float* bih0 = (const float*)d_in[4];
    const float* bhh0 = (const float*)d_in[5];
    const float* Wih1 = (const float*)d_in[6];
    const float* Whh1 = (const float*)d_in[7];
    const float* bih1 = (const float*)d_in[8];
    const float* bhh1 = (const float*)d_in[9];
    const float* fcw  = (const float*)d_in[10];
    const float* fcb  = (const float*)d_in[11];
    float* out = (float*)d_out;

    const int S1  = 4 * 128 * (64 * 2 + 16);    //  73728
    const int S23 = 4 * 128 * (128 * 2 + 16);   // 139264
    const int S4  = 6 * 128 * (128 * 2 + 16);   // 208896
    cudaFuncSetAttribute(lstm_stage1,  cudaFuncAttributeMaxDynamicSharedMemorySize, S1);
    cudaFuncSetAttribute(lstm_stage23, cudaFuncAttributeMaxDynamicSharedMemorySize, S23);
    cudaFuncSetAttribute(lstm_stage4,  cudaFuncAttributeMaxDynamicSharedMemorySize, S4);

    prep_pack<<<256, 256>>>(Wih0, Whh0, Wih1, Whh1, bih0, bhh0, bih1, bhh1, fcw, fcb);
    prep_mug<<<64, 512>>>(mu, Wih0, bih0, bhh0);
    prep_x<<<4096, 256>>>(x);

    lstm_stage1 <<<dim3(512, 4), 512, S1 >>>();
    lstm_stage23<<<dim3(512, 8), 512, S23>>>();
    lstm_stage4 <<<dim3(512, 4), 512, S4 >>>();

    fc_reduce<<<256, 256>>>(out);
}

// round 7
// speedup vs baseline: 3.2669x; 2.0698x over previous
#include <cuda_runtime.h>
#include <cuda_fp16.h>
#include <cstdint>

// ============================================================================
// Forecaster via warp mma.sync, single-pass fp16 (f32 accumulate).
// Error budget: fp16 rounding -> gate err ~4e-4 RMS -> final rel_err ~1e-4,
// 10x under the 1e-3 threshold (vs 2.6e-6 with 3-pass bf16 at 3x the work).
//
// Stage 1: x  @ W0i' (K=64)  + bias0 -> h1, c1
// Stage 2: h1 @ W0h' (K=128) + mug[b] (c1) -> h2     } merged launch
// Stage 3: h1 @ W1i' (K=128) + bias1 -> h1p, c1p     }
// Stage 4: h2 @ W1i' + h1p @ W1h' + bias1 -> relu -> FC partials -> reduce
// Gate-interleaved packing keeps the LSTM cell 100% thread-local.
// ============================================================================

#define NROWS 65536

// ---------------- device scratch (allocation-free, 16B aligned) ----------------
__device__ __align__(16) __half d_W0i[512 * 64];
__device__ __align__(16) __half d_W0h[512 * 128];
__device__ __align__(16) __half d_W1i[512 * 128];
__device__ __align__(16) __half d_W1h[512 * 128];
__device__ float d_bias0p[512], d_bias1p[512];
__device__ float d_mug[64 * 512];
__device__ float d_fcw[128];
__device__ float d_fcb_v;

__device__ __align__(16) __half d_x16[NROWS * 64];
__device__ __align__(16) __half d_h1[NROWS * 128];
__device__ __align__(16) __half d_h2[NROWS * 128];
__device__ __align__(16) __half d_h1p[NROWS * 128];
__device__ __half d_c1[NROWS * 128];
__device__ __half d_c1p[NROWS * 128];
__device__ float d_fcpart[16 * NROWS];

// ---------------- helpers ----------------
__device__ __forceinline__ uint32_t smem_u32(const void* p) {
    uint32_t a;
    asm("{ .reg .u64 t; cvta.to.shared.u64 t, %1; cvt.u32.u64 %0, t; }"
        : "=r"(a) : "l"(p));
    return a;
}
__device__ __forceinline__ void ldsm4(uint32_t* r, uint32_t a) {
    asm volatile("ldmatrix.sync.aligned.m8n8.x4.shared.b16 {%0,%1,%2,%3}, [%4];"
                 : "=r"(r[0]), "=r"(r[1]), "=r"(r[2]), "=r"(r[3]) : "r"(a));
}
__device__ __forceinline__ void mma16816(float* d, const uint32_t* a, const uint32_t* b) {
    asm volatile(
        "mma.sync.aligned.m16n8k16.row.col.f32.f16.f16.f32 "
        "{%0,%1,%2,%3}, {%4,%5,%6,%7}, {%8,%9}, {%0,%1,%2,%3};"
        : "+f"(d[0]), "+f"(d[1]), "+f"(d[2]), "+f"(d[3])
        : "r"(a[0]), "r"(a[1]), "r"(a[2]), "r"(a[3]), "r"(b[0]), "r"(b[1]));
}
#define CP_COMMIT() asm volatile("cp.async.commit_group;" ::: "memory")
#define CP_WAIT(n)  asm volatile("cp.async.wait_group %0;" :: "n"(n) : "memory")

__device__ __forceinline__ float sigm_f(float x) {
    return __fdividef(1.0f, 1.0f + __expf(-x));
}
__device__ __forceinline__ float tanh_f(float x) {
    return __fdividef(2.0f, 1.0f + __expf(-2.0f * x)) - 1.0f;
}

// packed-column mapping: c' -> (gate, unit j). Gates order (i,f,g,o).
__device__ __forceinline__ void cmap(int c_, int& gate, int& j) {
    int chunk = c_ >> 7, r = c_ & 127, cg = (r >> 6) & 1, s = r & 63;
    int t = s >> 3, c = s & 7, p = t >> 1, th = t & 1, q = c >> 1, par = c & 1;
    gate = th * 2 + par;
    j = (chunk << 5) + (cg << 4) + (p << 2) + q;
}

// ============================================================================
// Prep kernels
// ============================================================================
__global__ void prep_pack(const float* __restrict__ Wih0, const float* __restrict__ Whh0,
                          const float* __restrict__ Wih1, const float* __restrict__ Whh1,
                          const float* __restrict__ bih0, const float* __restrict__ bhh0,
                          const float* __restrict__ bih1, const float* __restrict__ bhh1,
                          const float* __restrict__ fcw, const float* __restrict__ fcb) {
    int i = blockIdx.x * 256 + threadIdx.x;    // 65536 threads
    int c_ = i >> 7, k = i & 127;
    int gate, j;
    cmap(c_, gate, j);
    int G = gate * 128 + j;
    d_W0h[c_ * 128 + k] = __float2half_rn(Whh0[G * 128 + k]);
    d_W1i[c_ * 128 + k] = __float2half_rn(Wih1[G * 128 + k]);
    d_W1h[c_ * 128 + k] = __float2half_rn(Whh1[G * 128 + k]);
    if (k < 64) d_W0i[c_ * 64 + k] = __float2half_rn(Wih0[G * 64 + k]);
    if (k == 0) {
        d_bias0p[c_] = bih0[G] + bhh0[G];
        d_bias1p[c_] = bih1[G] + bhh1[G];
    }
    if (i < 128) d_fcw[i] = fcw[i];
    if (i == 0) d_fcb_v = fcb[0];
}

__global__ void prep_mug(const float* __restrict__ mu,
                         const float* __restrict__ Wih0,
                         const float* __restrict__ bih0,
                         const float* __restrict__ bhh0) {
    __shared__ float mur[64];
    int c_ = threadIdx.x;
    if (c_ < 64) mur[c_] = mu[blockIdx.x * 64 + c_];
    __syncthreads();
    int gate, j;
    cmap(c_, gate, j);
    int G = gate * 128 + j;
    float s = bih0[G] + bhh0[G];
    const float* wr = Wih0 + G * 64;
#pragma unroll
    for (int k = 0; k < 64; k++) s = fmaf(mur[k], wr[k], s);
    d_mug[blockIdx.x * 512 + c_] = s;
}

__global__ void prep_x(const float* __restrict__ x) {
    int i = blockIdx.x * 256 + threadIdx.x;      // x4 elems each
    float4 v = reinterpret_cast<const float4*>(x)[i];
    __half2 p01 = __floats2half2_rn(v.x, v.y);
    __half2 p23 = __floats2half2_rn(v.z, v.w);
    reinterpret_cast<uint2*>(d_x16)[i] =
        make_uint2(*reinterpret_cast<uint32_t*>(&p01), *reinterpret_cast<uint32_t*>(&p23));
}

// ============================================================================
// cp.async SMEM fill: 128 rows x KT fp16, padded stride ST = 2*KT+16 bytes
// ============================================================================
template <int KT>
__device__ __forceinline__ void cp_fill(uint32_t sdst, const __half* __restrict__ g,
                                        int row0, int tid) {
    constexpr int ST = KT * 2 + 16;
    constexpr int CPR = KT / 8;                  // 16B chunks per row
    constexpr int ITER = 128 * CPR / 512;
#pragma unroll
    for (int t = 0; t < ITER; t++) {
        int e = tid + t * 512;
        int row = e / CPR;
        int kq = (e % CPR) * 8;
        uint32_t d = sdst + (uint32_t)row * ST + (uint32_t)kq * 2;
        const void* s = g + (size_t)(row0 + row) * KT + kq;
        asm volatile("cp.async.cg.shared.global [%0], [%1], 16;" :: "r"(d), "l"(s));
    }
}

// ============================================================================
// MMA sweep: warp tile 32 rows x 32 cols, acc[2][4][4]
// ============================================================================
template <int KT>
__device__ __forceinline__ void sweep(uint32_t sA, uint32_t sB, int lane,
                                      int m0, int n0, float (&acc)[2][4][4]) {
    constexpr int ST = KT * 2 + 16;
    const uint32_t lrow = (uint32_t)(lane & 15);
    const uint32_t lhi = (uint32_t)(lane >> 4) * 16u;
    const uint32_t aB0 = sA + (m0 + lrow) * ST + lhi;
    const uint32_t aB1 = aB0 + 16 * ST;
    const uint32_t bB0 = sB + (n0 + lrow) * ST + lhi;
    const uint32_t bB1 = bB0 + 16 * ST;
#pragma unroll
    for (int kc = 0; kc < KT / 16; kc++) {
        const uint32_t ko = kc * 32;
        uint32_t a0[4], a1[4], b0[4], b1[4];
        ldsm4(a0, aB0 + ko);
        ldsm4(a1, aB1 + ko);
        ldsm4(b0, bB0 + ko);
        ldsm4(b1, bB1 + ko);
        uint32_t be0[2] = {b0[0], b0[2]}, bo0[2] = {b0[1], b0[3]};
        uint32_t be1[2] = {b1[0], b1[2]}, bo1[2] = {b1[1], b1[3]};
        mma16816(acc[0][0], a0, be0); mma16816(acc[1][0], a1, be0);
        mma16816(acc[0][1], a0, bo0); mma16816(acc[1][1], a1, bo0);
        mma16816(acc[0][2], a0, be1); mma16816(acc[1][2], a1, be1);
        mma16816(acc[0][3], a0, bo1); mma16816(acc[1][3], a1, bo1);
    }
}

// ============================================================================
// Epilogue (thread-local LSTM cell; MODE 1:h1/c1  2:h2(c1)  3:h1p/c1p  4:fc(c1p))
// ============================================================================
template <int MODE>
__device__ __forceinline__ void epilogue(const float (&acc)[2][4][4],
                                         const float* s_add, const float* s_fcw,
                                         int row0, int chunk, int rg, int cg, int lane) {
    const int q = lane & 3;
    float fc[4] = {0.0f, 0.0f, 0.0f, 0.0f};
#pragma unroll
    for (int mt = 0; mt < 2; mt++) {
#pragma unroll
        for (int pr = 0; pr < 2; pr++) {
            const int aidx = cg * 32 + pr * 16 + q * 2;
            const float addi = s_add[aidx];
            const float addf = s_add[aidx + 1];
            const float addg = s_add[aidx + 8];
            const float addo = s_add[aidx + 9];
            const int j = chunk * 32 + (cg * 2 + pr) * 4 + q;
#pragma unroll
            for (int h2 = 0; h2 < 2; h2++) {
                const int row = row0 + rg * 32 + mt * 16 + (lane >> 2) + h2 * 8;
                const size_t idx = (size_t)row * 128 + j;
                float gi = acc[mt][2 * pr][h2 * 2 + 0] + addi;
                float gf = acc[mt][2 * pr][h2 * 2 + 1] + addf;
                float gg = acc[mt][2 * pr + 1][h2 * 2 + 0] + addg;
                float go = acc[mt][2 * pr + 1][h2 * 2 + 1] + addo;
                float cn;
                if (MODE == 1 || MODE == 3) {
                    cn = sigm_f(gi) * tanh_f(gg);
                } else {
                    const float cp = __half2float((MODE == 2) ? d_c1[idx] : d_c1p[idx]);
                    cn = sigm_f(gf) * cp + sigm_f(gi) * tanh_f(gg);
                }
                float hn = sigm_f(go) * tanh_f(cn);
                if (MODE == 4) {
                    fc[mt * 2 + h2] = fmaf(fmaxf(hn, 0.0f), s_fcw[(cg * 2 + pr) * 4 + q],
                                           fc[mt * 2 + h2]);
                } else {
                    __half h = __float2half_rn(hn);
                    __half c = __float2half_rn(cn);
                    if (MODE == 1) { d_h1[idx] = h;  d_c1[idx] = c; }
                    if (MODE == 2) { d_h2[idx] = h; }
                    if (MODE == 3) { d_h1p[idx] = h; d_c1p[idx] = c; }
                }
            }
        }
    }
    if (MODE == 4) {
#pragma unroll
        for (int s = 0; s < 4; s++) {
            float v = fc[s];
            v += __shfl_xor_sync(0xffffffffu, v, 1);
            v += __shfl_xor_sync(0xffffffffu, v, 2);
            if (q == 0) {
                const int row = row0 + rg * 32 + (s >> 1) * 16 + (lane >> 2) + (s & 1) * 8;
                d_fcpart[(chunk * 4 + cg) * NROWS + row] = v;
            }
        }
    }
}

// ============================================================================
// Stage 1: x @ W0i' (K=64) -> h1, c1.   grid (512, 4), 512 threads
// ============================================================================
__global__ void __launch_bounds__(512) lstm_stage1() {
    extern __shared__ __align__(128) char dsm[];
    __shared__ float s_add[128];
    constexpr int KT = 64, ST = KT * 2 + 16, TILE = 128 * ST;

    const int tid = threadIdx.x, lane = tid & 31, wid = tid >> 5;
    const int rg = wid >> 2, cg = wid & 3;
    const int row0 = blockIdx.x * 128, chunk = blockIdx.y;
    const uint32_t s0 = smem_u32(dsm);
    const uint32_t sA = s0, sB = s0 + TILE;

    if (tid < 128) s_add[tid] = d_bias0p[chunk * 128 + tid];

    cp_fill<KT>(sA, d_x16, row0, tid);
    cp_fill<KT>(sB, d_W0i + chunk * 128 * KT, 0, tid);
    CP_COMMIT();

    float acc[2][4][4] = {};
    CP_WAIT(0); __syncthreads();
    sweep<KT>(sA, sB, lane, rg * 32, cg * 32, acc);

    epilogue<1>(acc, s_add, nullptr, row0, chunk, rg, cg, lane);
}

// ============================================================================
// Stages 2+3 merged: grid (512, 8); y<4 -> stage2 (W0h, mug, c1 -> h2),
//                    y>=4 -> stage3 (W1i, bias1 -> h1p, c1p)
// ============================================================================
__global__ void __launch_bounds__(512) lstm_stage23() {
    extern __shared__ __align__(128) char dsm[];
    __shared__ float s_add[128];
    constexpr int KT = 128, ST = KT * 2 + 16, TILE = 128 * ST;

    const int tid = threadIdx.x, lane = tid & 31, wid = tid >> 5;
    const int rg = wid >> 2, cg = wid & 3;
    const int row0 = blockIdx.x * 128;
    const bool is2 = blockIdx.y < 4;
    const int chunk = blockIdx.y & 3;
    const uint32_t s0 = smem_u32(dsm);
    const uint32_t sA = s0, sB = s0 + TILE;

    if (tid < 128) {
        const float* src = is2 ? (d_mug + (blockIdx.x >> 3) * 512) : d_bias1p;
        s_add[tid] = src[chunk * 128 + tid];
    }
    const __half* B = (is2 ? d_W0h : d_W1i) + chunk * 128 * KT;

    cp_fill<KT>(sA, d_h1, row0, tid);
    cp_fill<KT>(sB, B, 0, tid);
    CP_COMMIT();

    float acc[2][4][4] = {};
    CP_WAIT(0); __syncthreads();
    sweep<KT>(sA, sB, lane, rg * 32, cg * 32, acc);

    if (is2) epilogue<2>(acc, s_add, nullptr, row0, chunk, rg, cg, lane);
    else     epilogue<3>(acc, s_add, nullptr, row0, chunk, rg, cg, lane);
}

// ============================================================================
// Stage 4: h2 @ W1i' + h1p @ W1h' (K=256) -> relu -> FC partials
// grid (512, 4); all 4 tiles resident, single barrier.
// ============================================================================
__global__ void __launch_bounds__(512) lstm_stage4() {
    extern __shared__ __align__(128) char dsm[];
    __shared__ float s_add[128];
    __shared__ float s_fcw[32];
    constexpr int KT = 128, ST = KT * 2 + 16, TILE = 128 * ST;

    const int tid = threadIdx.x, lane = tid & 31, wid = tid >> 5;
    const int rg = wid >> 2, cg = wid & 3;
    const int row0 = blockIdx.x * 128, chunk = blockIdx.y;
    const uint32_t s0 = smem_u32(dsm);
    const uint32_t sA0 = s0, sB0 = s0 + TILE;
    const uint32_t sA1 = s0 + 2 * TILE, sB1 = s0 + 3 * TILE;

    if (tid < 128) s_add[tid] = d_bias1p[chunk * 128 + tid];
    if (tid < 32)  s_fcw[tid] = d_fcw[chunk * 32 + tid];

    cp_fill<KT>(sA0, d_h2, row0, tid);
    cp_fill<KT>(sB0, d_W1i + chunk * 128 * KT, 0, tid);
    CP_COMMIT();
    cp_fill<KT>(sA1, d_h1p, row0, tid);
    cp_fill<KT>(sB1, d_W1h + chunk * 128 * KT, 0, tid);
    CP_COMMIT();

    float acc[2][4][4] = {};
    const int m0 = rg * 32, n0 = cg * 32;
    CP_WAIT(1); __syncthreads();
    sweep<KT>(sA0, sB0, lane, m0, n0, acc);
    CP_WAIT(0); __syncthreads();
    sweep<KT>(sA1, sB1, lane, m0, n0, acc);

    epilogue<4>(acc, s_add, s_fcw, row0, chunk, rg, cg, lane);
}

// ============================================================================
// FC reduce: out[r] = fcb + sum of 16 partials (deterministic)
// ============================================================================
__global__ void fc_reduce(float* __restrict__ out) {
    int r = blockIdx.x * 256 + threadIdx.x;
    float s = d_fcb_v;
#pragma unroll
    for (int i = 0; i < 16; i++) s += d_fcpart[i * NROWS + r];
    out[r] = s;
}

// ============================================================================
// Launch
// ============================================================================
extern "C" void kernel_launch(void* const* d_in, const int* in_sizes, int n_in,
                              void* d_out, int out_size) {
    const float* x    = (const float*)d_in[0];
    const float* mu   = (const float*)d_in[1];
    const float* Wih0 = (const float*)d_in[2];
    const float* Whh0 = (const float*)d_in[3];
    const float* bih0 = (const float*)d_in[4];
    const float* bhh0 = (const float*)d_in[5];
    const float* Wih1 = (const float*)d_in[6];
    const float* Whh1 = (const float*)d_in[7];
    const float* bih1 = (const float*)d_in[8];
    const float* bhh1 = (const float*)d_in[9];
    const float* fcw  = (const float*)d_in[10];
    const float* fcb  = (const float*)d_in[11];
    float* out = (float*)d_out;

    const int S1  = 2 * 128 * (64 * 2 + 16);    //  36864
    const int S23 = 2 * 128 * (128 * 2 + 16);   //  69632
    const int S4  = 4 * 128 * (128 * 2 + 16);   // 139264
    cudaFuncSetAttribute(lstm_stage1,  cudaFuncAttributeMaxDynamicSharedMemorySize, S1);
    cudaFuncSetAttribute(lstm_stage23, cudaFuncAttributeMaxDynamicSharedMemorySize, S23);
    cudaFuncSetAttribute(lstm_stage4,  cudaFuncAttributeMaxDynamicSharedMemorySize, S4);

    prep_pack<<<256, 256>>>(Wih0, Whh0, Wih1, Whh1, bih0, bhh0, bih1, bhh1, fcw, fcb);
    prep_mug<<<64, 512>>>(mu, Wih0, bih0, bhh0);
    prep_x<<<4096, 256>>>(x);

    lstm_stage1 <<<dim3(512, 4), 512, S1 >>>();
    lstm_stage23<<<dim3(512, 8), 512, S23>>>();
    lstm_stage4 <<<dim3(512, 4), 512, S4 >>>();

    fc_reduce<<<256, 256>>>(out);
}

// round 8
// speedup vs baseline: 3.3187x; 1.0158x over previous
#include <cuda_runtime.h>
#include <cuda_fp16.h>
#include <cstdint>

// ============================================================================
// Forecaster, warp mma.sync fp16 (f32 accum), v3:
//  - persistent-chunk CTAs: weight tile loaded ONCE per CTA, 4 row-blocks loop
//  - A tiles double-buffered via cp.async prefetch (overlap fill with MMA)
//  - launch_bounds(512,2) -> 2 CTAs/SM for stages 1/23
// ============================================================================

#define NROWS 65536

// ---------------- device scratch (allocation-free, 16B aligned) ----------------
__device__ __align__(16) __half d_W0i[512 * 64];
__device__ __align__(16) __half d_W0h[512 * 128];
__device__ __align__(16) __half d_W1i[512 * 128];
__device__ __align__(16) __half d_W1h[512 * 128];
__device__ float d_bias0p[512], d_bias1p[512];
__device__ float d_mug[64 * 512];
__device__ float d_fcw[128];
__device__ float d_fcb_v;

__device__ __align__(16) __half d_x16[NROWS * 64];
__device__ __align__(16) __half d_h1[NROWS * 128];
__device__ __align__(16) __half d_h2[NROWS * 128];
__device__ __align__(16) __half d_h1p[NROWS * 128];
__device__ __half d_c1[NROWS * 128];
__device__ __half d_c1p[NROWS * 128];
__device__ float d_fcpart[16 * NROWS];

// ---------------- helpers ----------------
__device__ __forceinline__ uint32_t smem_u32(const void* p) {
    uint32_t a;
    asm("{ .reg .u64 t; cvta.to.shared.u64 t, %1; cvt.u32.u64 %0, t; }"
        : "=r"(a) : "l"(p));
    return a;
}
__device__ __forceinline__ void ldsm4(uint32_t* r, uint32_t a) {
    asm volatile("ldmatrix.sync.aligned.m8n8.x4.shared.b16 {%0,%1,%2,%3}, [%4];"
                 : "=r"(r[0]), "=r"(r[1]), "=r"(r[2]), "=r"(r[3]) : "r"(a));
}
__device__ __forceinline__ void mma16816(float* d, const uint32_t* a, const uint32_t* b) {
    asm volatile(
        "mma.sync.aligned.m16n8k16.row.col.f32.f16.f16.f32 "
        "{%0,%1,%2,%3}, {%4,%5,%6,%7}, {%8,%9}, {%0,%1,%2,%3};"
        : "+f"(d[0]), "+f"(d[1]), "+f"(d[2]), "+f"(d[3])
        : "r"(a[0]), "r"(a[1]), "r"(a[2]), "r"(a[3]), "r"(b[0]), "r"(b[1]));
}
#define CP_COMMIT() asm volatile("cp.async.commit_group;" ::: "memory")
#define CP_WAIT(n)  asm volatile("cp.async.wait_group %0;" :: "n"(n) : "memory")

__device__ __forceinline__ float sigm_f(float x) {
    return __fdividef(1.0f, 1.0f + __expf(-x));
}
__device__ __forceinline__ float tanh_f(float x) {
    return __fdividef(2.0f, 1.0f + __expf(-2.0f * x)) - 1.0f;
}

// packed-column mapping: c' -> (gate, unit j). Gates order (i,f,g,o).
__device__ __forceinline__ void cmap(int c_, int& gate, int& j) {
    int chunk = c_ >> 7, r = c_ & 127, cg = (r >> 6) & 1, s = r & 63;
    int t = s >> 3, c = s & 7, p = t >> 1, th = t & 1, q = c >> 1, par = c & 1;
    gate = th * 2 + par;
    j = (chunk << 5) + (cg << 4) + (p << 2) + q;
}

// ============================================================================
// Prep kernels
// ============================================================================
__global__ void prep_pack(const float* __restrict__ Wih0, const float* __restrict__ Whh0,
                          const float* __restrict__ Wih1, const float* __restrict__ Whh1,
                          const float* __restrict__ bih0, const float* __restrict__ bhh0,
                          const float* __restrict__ bih1, const float* __restrict__ bhh1,
                          const float* __restrict__ fcw, const float* __restrict__ fcb) {
    int i = blockIdx.x * 256 + threadIdx.x;    // 65536 threads
    int c_ = i >> 7, k = i & 127;
    int gate, j;
    cmap(c_, gate, j);
    int G = gate * 128 + j;
    d_W0h[c_ * 128 + k] = __float2half_rn(Whh0[G * 128 + k]);
    d_W1i[c_ * 128 + k] = __float2half_rn(Wih1[G * 128 + k]);
    d_W1h[c_ * 128 + k] = __float2half_rn(Whh1[G * 128 + k]);
    if (k < 64) d_W0i[c_ * 64 + k] = __float2half_rn(Wih0[G * 64 + k]);
    if (k == 0) {
        d_bias0p[c_] = bih0[G] + bhh0[G];
        d_bias1p[c_] = bih1[G] + bhh1[G];
    }
    if (i < 128) d_fcw[i] = fcw[i];
    if (i == 0) d_fcb_v = fcb[0];
}

__global__ void prep_mug(const float* __restrict__ mu,
                         const float* __restrict__ Wih0,
                         const float* __restrict__ bih0,
                         const float* __restrict__ bhh0) {
    __shared__ float mur[64];
    int c_ = threadIdx.x;
    if (c_ < 64) mur[c_] = mu[blockIdx.x * 64 + c_];
    __syncthreads();
    int gate, j;
    cmap(c_, gate, j);
    int G = gate * 128 + j;
    float s = bih0[G] + bhh0[G];
    const float* wr = Wih0 + G * 64;
#pragma unroll
    for (int k = 0; k < 64; k++) s = fmaf(mur[k], wr[k], s);
    d_mug[blockIdx.x * 512 + c_] = s;
}

__global__ void prep_x(const float* __restrict__ x) {
    int i = blockIdx.x * 256 + threadIdx.x;      // x4 elems each
    float4 v = reinterpret_cast<const float4*>(x)[i];
    __half2 p01 = __floats2half2_rn(v.x, v.y);
    __half2 p23 = __floats2half2_rn(v.z, v.w);
    reinterpret_cast<uint2*>(d_x16)[i] =
        make_uint2(*reinterpret_cast<uint32_t*>(&p01), *reinterpret_cast<uint32_t*>(&p23));
}

// ============================================================================
// cp.async SMEM fill: 128 rows x KT fp16, padded stride ST = 2*KT+16 bytes
// ============================================================================
template <int KT>
__device__ __forceinline__ void cp_fill(uint32_t sdst, const __half* __restrict__ g,
                                        int row0, int tid) {
    constexpr int ST = KT * 2 + 16;
    constexpr int CPR = KT / 8;                  // 16B chunks per row
    constexpr int ITER = 128 * CPR / 512;
#pragma unroll
    for (int t = 0; t < ITER; t++) {
        int e = tid + t * 512;
        int row = e / CPR;
        int kq = (e % CPR) * 8;
        uint32_t d = sdst + (uint32_t)row * ST + (uint32_t)kq * 2;
        const void* s = g + (size_t)(row0 + row) * KT + kq;
        asm volatile("cp.async.cg.shared.global [%0], [%1], 16;" :: "r"(d), "l"(s));
    }
}

// ============================================================================
// MMA sweep: warp tile 32 rows x 32 cols, acc[2][4][4]
// ============================================================================
template <int KT>
__device__ __forceinline__ void sweep(uint32_t sA, uint32_t sB, int lane,
                                      int m0, int n0, float (&acc)[2][4][4]) {
    constexpr int ST = KT * 2 + 16;
    const uint32_t lrow = (uint32_t)(lane & 15);
    const uint32_t lhi = (uint32_t)(lane >> 4) * 16u;
    const uint32_t aB0 = sA + (m0 + lrow) * ST + lhi;
    const uint32_t aB1 = aB0 + 16 * ST;
    const uint32_t bB0 = sB + (n0 + lrow) * ST + lhi;
    const uint32_t bB1 = bB0 + 16 * ST;
#pragma unroll
    for (int kc = 0; kc < KT / 16; kc++) {
        const uint32_t ko = kc * 32;
        uint32_t a0[4], a1[4], b0[4], b1[4];
        ldsm4(a0, aB0 + ko);
        ldsm4(a1, aB1 + ko);
        ldsm4(b0, bB0 + ko);
        ldsm4(b1, bB1 + ko);
        uint32_t be0[2] = {b0[0], b0[2]}, bo0[2] = {b0[1], b0[3]};
        uint32_t be1[2] = {b1[0], b1[2]}, bo1[2] = {b1[1], b1[3]};
        mma16816(acc[0][0], a0, be0); mma16816(acc[1][0], a1, be0);
        mma16816(acc[0][1], a0, bo0); mma16816(acc[1][1], a1, bo0);
        mma16816(acc[0][2], a0, be1); mma16816(acc[1][2], a1, be1);
        mma16816(acc[0][3], a0, bo1); mma16816(acc[1][3], a1, bo1);
    }
}

// ============================================================================
// Epilogue (thread-local LSTM cell; MODE 1:h1/c1  2:h2(c1)  3:h1p/c1p  4:fc(c1p))
// ============================================================================
template <int MODE>
__device__ __forceinline__ void epilogue(const float (&acc)[2][4][4],
                                         const float* s_add, const float* s_fcw,
                                         int row0, int chunk, int rg, int cg, int lane) {
    const int q = lane & 3;
    float fc[4] = {0.0f, 0.0f, 0.0f, 0.0f};
#pragma unroll
    for (int mt = 0; mt < 2; mt++) {
#pragma unroll
        for (int pr = 0; pr < 2; pr++) {
            const int aidx = cg * 32 + pr * 16 + q * 2;
            const float addi = s_add[aidx];
            const float addf = s_add[aidx + 1];
            const float addg = s_add[aidx + 8];
            const float addo = s_add[aidx + 9];
            const int j = chunk * 32 + (cg * 2 + pr) * 4 + q;
#pragma unroll
            for (int h2 = 0; h2 < 2; h2++) {
                const int row = row0 + rg * 32 + mt * 16 + (lane >> 2) + h2 * 8;
                const size_t idx = (size_t)row * 128 + j;
                float gi = acc[mt][2 * pr][h2 * 2 + 0] + addi;
                float gf = acc[mt][2 * pr][h2 * 2 + 1] + addf;
                float gg = acc[mt][2 * pr + 1][h2 * 2 + 0] + addg;
                float go = acc[mt][2 * pr + 1][h2 * 2 + 1] + addo;
                float cn;
                if (MODE == 1 || MODE == 3) {
                    cn = sigm_f(gi) * tanh_f(gg);
                } else {
                    const float cp = __half2float((MODE == 2) ? d_c1[idx] : d_c1p[idx]);
                    cn = sigm_f(gf) * cp + sigm_f(gi) * tanh_f(gg);
                }
                float hn = sigm_f(go) * tanh_f(cn);
                if (MODE == 4) {
                    fc[mt * 2 + h2] = fmaf(fmaxf(hn, 0.0f), s_fcw[(cg * 2 + pr) * 4 + q],
                                           fc[mt * 2 + h2]);
                } else {
                    __half h = __float2half_rn(hn);
                    __half c = __float2half_rn(cn);
                    if (MODE == 1) { d_h1[idx] = h;  d_c1[idx] = c; }
                    if (MODE == 2) { d_h2[idx] = h; }
                    if (MODE == 3) { d_h1p[idx] = h; d_c1p[idx] = c; }
                }
            }
        }
    }
    if (MODE == 4) {
#pragma unroll
        for (int s = 0; s < 4; s++) {
            float v = fc[s];
            v += __shfl_xor_sync(0xffffffffu, v, 1);
            v += __shfl_xor_sync(0xffffffffu, v, 2);
            if (q == 0) {
                const int row = row0 + rg * 32 + (s >> 1) * 16 + (lane >> 2) + (s & 1) * 8;
                d_fcpart[(chunk * 4 + cg) * NROWS + row] = v;
            }
        }
    }
}

// ============================================================================
// Stage 1: x @ W0i' (K=64) -> h1, c1.
// grid (128, 4): CTA owns one gate chunk, loops 4 row-blocks; B resident,
// A double-buffered with cp.async prefetch.
// ============================================================================
__global__ void __launch_bounds__(512, 2) lstm_stage1() {
    extern __shared__ __align__(128) char dsm[];
    __shared__ float s_add[128];
    constexpr int KT = 64, ST = KT * 2 + 16, TILE = 128 * ST;

    const int tid = threadIdx.x, lane = tid & 31, wid = tid >> 5;
    const int rg = wid >> 2, cg = wid & 3;
    const int chunk = blockIdx.y;
    const uint32_t s0 = smem_u32(dsm);
    const uint32_t sB = s0;
    const uint32_t sA[2] = {s0 + TILE, s0 + 2 * TILE};

    if (tid < 128) s_add[tid] = d_bias0p[chunk * 128 + tid];

    cp_fill<KT>(sB, d_W0i + chunk * 128 * KT, 0, tid);
    cp_fill<KT>(sA[0], d_x16, blockIdx.x * 4 * 128, tid);
    CP_COMMIT();

#pragma unroll
    for (int rb = 0; rb < 4; rb++) {
        const int row0 = (blockIdx.x * 4 + rb) * 128;
        if (rb < 3) { cp_fill<KT>(sA[(rb + 1) & 1], d_x16, row0 + 128, tid); CP_COMMIT(); }
        if (rb < 3) { CP_WAIT(1); } else { CP_WAIT(0); }
        __syncthreads();
        float acc[2][4][4] = {};
        sweep<KT>(sA[rb & 1], sB, lane, rg * 32, cg * 32, acc);
        epilogue<1>(acc, s_add, nullptr, row0, chunk, rg, cg, lane);
        __syncthreads();
    }
}

// ============================================================================
// Stages 2+3 merged: grid (128, 8); y<4 -> stage2 (W0h, mug, c1 -> h2),
//                    y>=4 -> stage3 (W1i, bias1 -> h1p, c1p). Loop 4 row-blocks.
// ============================================================================
__global__ void __launch_bounds__(512, 2) lstm_stage23() {
    extern __shared__ __align__(128) char dsm[];
    __shared__ float s_add[128];
    constexpr int KT = 128, ST = KT * 2 + 16, TILE = 128 * ST;

    const int tid = threadIdx.x, lane = tid & 31, wid = tid >> 5;
    const int rg = wid >> 2, cg = wid & 3;
    const bool is2 = blockIdx.y < 4;
    const int chunk = blockIdx.y & 3;
    const uint32_t s0 = smem_u32(dsm);
    const uint32_t sB = s0;
    const uint32_t sA[2] = {s0 + TILE, s0 + 2 * TILE};

    if (!is2 && tid < 128) s_add[tid] = d_bias1p[chunk * 128 + tid];
    const __half* B = (is2 ? d_W0h : d_W1i) + chunk * 128 * KT;

    cp_fill<KT>(sB, B, 0, tid);
    cp_fill<KT>(sA[0], d_h1, blockIdx.x * 4 * 128, tid);
    CP_COMMIT();

#pragma unroll
    for (int rb = 0; rb < 4; rb++) {
        const int row0 = (blockIdx.x * 4 + rb) * 128;
        if (is2 && tid < 128)
            s_add[tid] = d_mug[(row0 >> 10) * 512 + chunk * 128 + tid];
        if (rb < 3) { cp_fill<KT>(sA[(rb + 1) & 1], d_h1, row0 + 128, tid); CP_COMMIT(); }
        if (rb < 3) { CP_WAIT(1); } else { CP_WAIT(0); }
        __syncthreads();
        float acc[2][4][4] = {};
        sweep<KT>(sA[rb & 1], sB, lane, rg * 32, cg * 32, acc);
        if (is2) epilogue<2>(acc, s_add, nullptr, row0, chunk, rg, cg, lane);
        else     epilogue<3>(acc, s_add, nullptr, row0, chunk, rg, cg, lane);
        __syncthreads();
    }
}

// ============================================================================
// Stage 4: h2 @ W1i' + h1p @ W1h' (K=256) -> relu -> FC partials.
// grid (128, 4): both B tiles resident; A prefetch alternates h2/h1p streams.
// ============================================================================
__global__ void __launch_bounds__(512, 1) lstm_stage4() {
    extern __shared__ __align__(128) char dsm[];
    __shared__ float s_add[128];
    __shared__ float s_fcw[32];
    constexpr int KT = 128, ST = KT * 2 + 16, TILE = 128 * ST;

    const int tid = threadIdx.x, lane = tid & 31, wid = tid >> 5;
    const int rg = wid >> 2, cg = wid & 3;
    const int chunk = blockIdx.y;
    const uint32_t s0 = smem_u32(dsm);
    const uint32_t sB[2] = {s0, s0 + TILE};
    const uint32_t sA[2] = {s0 + 2 * TILE, s0 + 3 * TILE};

    if (tid < 128) s_add[tid] = d_bias1p[chunk * 128 + tid];
    if (tid < 32)  s_fcw[tid] = d_fcw[chunk * 32 + tid];

    cp_fill<KT>(sB[0], d_W1i + chunk * 128 * KT, 0, tid);
    cp_fill<KT>(sB[1], d_W1h + chunk * 128 * KT, 0, tid);
    cp_fill<KT>(sA[0], d_h2, blockIdx.x * 4 * 128, tid);
    CP_COMMIT();

    const int m0 = rg * 32, n0 = cg * 32;
#pragma unroll
    for (int rb = 0; rb < 4; rb++) {
        const int row0 = (blockIdx.x * 4 + rb) * 128;
        float acc[2][4][4] = {};
#pragma unroll
        for (int src = 0; src < 2; src++) {
            const int t = rb * 2 + src;
            if (t < 7) {
                const __half* nA = ((t + 1) & 1) ? d_h1p : d_h2;
                const int nrow = (blockIdx.x * 4 + ((t + 1) >> 1)) * 128;
                cp_fill<KT>(sA[(t + 1) & 1], nA, nrow, tid);
                CP_COMMIT();
            }
            if (t < 7) { CP_WAIT(1); } else { CP_WAIT(0); }
            __syncthreads();
            sweep<KT>(sA[t & 1], sB[src], lane, m0, n0, acc);
            if (src == 1) epilogue<4>(acc, s_add, s_fcw, row0, chunk, rg, cg, lane);
            __syncthreads();
        }
    }
}

// ============================================================================
// FC reduce: out[r] = fcb + sum of 16 partials (deterministic)
// ============================================================================
__global__ void fc_reduce(float* __restrict__ out) {
    int r = blockIdx.x * 256 + threadIdx.x;
    float s = d_fcb_v;
#pragma unroll
    for (int i = 0; i < 16; i++) s += d_fcpart[i * NROWS + r];
    out[r] = s;
}

// ============================================================================
// Launch
// ============================================================================
extern "C" void kernel_launch(void* const* d_in, const int* in_sizes, int n_in,
                              void* d_out, int out_size) {
    const float* x    = (const float*)d_in[0];
    const float* mu   = (const float*)d_in[1];
    const float* Wih0 = (const float*)d_in[2];
    const float* Whh0 = (const float*)d_in[3];
    const float* bih0 = (const float*)d_in[4];
    const float* bhh0 = (const float*)d_in[5];
    const float* Wih1 = (const float*)d_in[6];
    const float* Whh1 = (const float*)d_in[7];
    const float* bih1 = (const float*)d_in[8];
    const float* bhh1 = (const float*)d_in[9];
    const float* fcw  = (const float*)d_in[10];
    const float* fcb  = (const float*)d_in[11];
    float* out = (float*)d_out;

    const int S1  = 3 * 128 * (64 * 2 + 16);    //  55296
    const int S23 = 3 * 128 * (128 * 2 + 16);   // 104448
    const int S4  = 4 * 128 * (128 * 2 + 16);   // 139264
    cudaFuncSetAttribute(lstm_stage1,  cudaFuncAttributeMaxDynamicSharedMemorySize, S1);
    cudaFuncSetAttribute(lstm_stage23, cudaFuncAttributeMaxDynamicSharedMemorySize, S23);
    cudaFuncSetAttribute(lstm_stage4,  cudaFuncAttributeMaxDynamicSharedMemorySize, S4);

    prep_pack<<<256, 256>>>(Wih0, Whh0, Wih1, Whh1, bih0, bhh0, bih1, bhh1, fcw, fcb);
    prep_mug<<<64, 512>>>(mu, Wih0, bih0, bhh0);
    prep_x<<<4096, 256>>>(x);

    lstm_stage1 <<<dim3(128, 4), 512, S1 >>>();
    lstm_stage23<<<dim3(128, 8), 512, S23>>>();
    lstm_stage4 <<<dim3(128, 4), 512, S4 >>>();

    fc_reduce<<<256, 256>>>(out);
}

// round 9
// speedup vs baseline: 4.2169x; 1.2706x over previous
#include <cuda_runtime.h>
#include <cuda_fp16.h>
#include <cstdint>

// ============================================================================
// Fully-fused Forecaster: one CTA owns 128 rows end-to-end.
//   stage1: x  @ W0i (K=64)  + bias0 -> h1 (SMEM), c1 (regs)
//   stage2: h1 @ W0h (K=128) + mug   -> h2 (SMEM)          [reads c1 regs]
//   stage3: h1 @ W1i (K=128) + bias1 -> h1p (SMEM), c1p (regs)
//   stage4: h2 @ W1i + h1p @ W1h + bias1 -> relu -> FC -> out
// Intermediates never touch global memory. Weights streamed from L2 with
// double-buffered cp.async. fp16 single-pass MMA (f32 accum).
// ============================================================================

#define NROWS 65536

// weights packed [512 packed gate-cols][K]; packing: c' = nc*128+cg*32+t*8+ct
// gate t in (i,f,g,o), unit j = nc*32+cg*8+ct
__device__ __align__(16) __half d_W0i[512 * 64];
__device__ __align__(16) __half d_W0h[512 * 128];
__device__ __align__(16) __half d_W1i[512 * 128];
__device__ __align__(16) __half d_W1h[512 * 128];
__device__ float d_bias0p[512], d_bias1p[512];
__device__ float d_mug[64 * 512];
__device__ float d_fcw[128];
__device__ float d_fcb_v;
__device__ __align__(16) __half d_x16[NROWS * 64];

// ---------------- helpers ----------------
__device__ __forceinline__ uint32_t smem_u32(const void* p) {
    uint32_t a;
    asm("{ .reg .u64 t; cvta.to.shared.u64 t, %1; cvt.u32.u64 %0, t; }"
        : "=r"(a) : "l"(p));
    return a;
}
__device__ __forceinline__ void ldsm4(uint32_t* r, uint32_t a) {
    asm volatile("ldmatrix.sync.aligned.m8n8.x4.shared.b16 {%0,%1,%2,%3}, [%4];"
                 : "=r"(r[0]), "=r"(r[1]), "=r"(r[2]), "=r"(r[3]) : "r"(a));
}
__device__ __forceinline__ void mma16816(float* d, const uint32_t* a, const uint32_t* b) {
    asm volatile(
        "mma.sync.aligned.m16n8k16.row.col.f32.f16.f16.f32 "
        "{%0,%1,%2,%3}, {%4,%5,%6,%7}, {%8,%9}, {%0,%1,%2,%3};"
        : "+f"(d[0]), "+f"(d[1]), "+f"(d[2]), "+f"(d[3])
        : "r"(a[0]), "r"(a[1]), "r"(a[2]), "r"(a[3]), "r"(b[0]), "r"(b[1]));
}
#define CP_COMMIT() asm volatile("cp.async.commit_group;" ::: "memory")
#define CP_WAIT0()  asm volatile("cp.async.wait_group 0;" ::: "memory")

__device__ __forceinline__ float sigm_f(float x) {
    return __fdividef(1.0f, 1.0f + __expf(-x));
}
__device__ __forceinline__ float tanh_f(float x) {
    return __fdividef(2.0f, 1.0f + __expf(-2.0f * x)) - 1.0f;
}

// packed-column mapping: c' -> (gate t, unit j)
__device__ __forceinline__ void cmap(int c_, int& gate, int& j) {
    int nc = c_ >> 7, cg = (c_ >> 5) & 3, t = (c_ >> 3) & 3, ct = c_ & 7;
    gate = t;
    j = nc * 32 + cg * 8 + ct;
}

// ============================================================================
// Prep kernels
// ============================================================================
__global__ void prep_pack(const float* __restrict__ Wih0, const float* __restrict__ Whh0,
                          const float* __restrict__ Wih1, const float* __restrict__ Whh1,
                          const float* __restrict__ bih0, const float* __restrict__ bhh0,
                          const float* __restrict__ bih1, const float* __restrict__ bhh1,
                          const float* __restrict__ fcw, const float* __restrict__ fcb) {
    int i = blockIdx.x * 256 + threadIdx.x;    // 65536 threads
    int c_ = i >> 7, k = i & 127;
    int gate, j;
    cmap(c_, gate, j);
    int G = gate * 128 + j;
    d_W0h[c_ * 128 + k] = __float2half_rn(Whh0[G * 128 + k]);
    d_W1i[c_ * 128 + k] = __float2half_rn(Wih1[G * 128 + k]);
    d_W1h[c_ * 128 + k] = __float2half_rn(Whh1[G * 128 + k]);
    if (k < 64) d_W0i[c_ * 64 + k] = __float2half_rn(Wih0[G * 64 + k]);
    if (k == 0) {
        d_bias0p[c_] = bih0[G] + bhh0[G];
        d_bias1p[c_] = bih1[G] + bhh1[G];
    }
    if (i < 128) d_fcw[i] = fcw[i];
    if (i == 0) d_fcb_v = fcb[0];
}

__global__ void prep_mug(const float* __restrict__ mu,
                         const float* __restrict__ Wih0,
                         const float* __restrict__ bih0,
                         const float* __restrict__ bhh0) {
    __shared__ float mur[64];
    int c_ = threadIdx.x;
    if (c_ < 64) mur[c_] = mu[blockIdx.x * 64 + c_];
    __syncthreads();
    int gate, j;
    cmap(c_, gate, j);
    int G = gate * 128 + j;
    float s = bih0[G] + bhh0[G];
    const float* wr = Wih0 + G * 64;
#pragma unroll
    for (int k = 0; k < 64; k++) s = fmaf(mur[k], wr[k], s);
    d_mug[blockIdx.x * 512 + c_] = s;
}

__global__ void prep_x(const float* __restrict__ x) {
    int i = blockIdx.x * 256 + threadIdx.x;
    float4 v = reinterpret_cast<const float4*>(x)[i];
    __half2 p01 = __floats2half2_rn(v.x, v.y);
    __half2 p23 = __floats2half2_rn(v.z, v.w);
    reinterpret_cast<uint2*>(d_x16)[i] =
        make_uint2(*reinterpret_cast<uint32_t*>(&p01), *reinterpret_cast<uint32_t*>(&p23));
}

// ============================================================================
// cp.async SMEM fill: 128 rows x KT fp16, stride ST = 2*KT+16
// ============================================================================
template <int KT>
__device__ __forceinline__ void cp_fill(uint32_t sdst, const __half* __restrict__ g,
                                        int row0, int tid) {
    constexpr int ST = KT * 2 + 16;
    constexpr int CPR = KT / 8;
    constexpr int ITER = 128 * CPR / 512;
#pragma unroll
    for (int t = 0; t < ITER; t++) {
        int e = tid + t * 512;
        int row = e / CPR;
        int kq = (e % CPR) * 8;
        uint32_t d = sdst + (uint32_t)row * ST + (uint32_t)kq * 2;
        const void* s = g + (size_t)(row0 + row) * KT + kq;
        asm volatile("cp.async.cg.shared.global [%0], [%1], 16;" :: "r"(d), "l"(s));
    }
}

// ============================================================================
// MMA sweep: warp tile 32 rows x 32 packed cols (= 4 gates x 8 units)
// acc[mt][tile t = gate][h2*2 + u]
// ============================================================================
template <int KT>
__device__ __forceinline__ void sweep(uint32_t sA, uint32_t sB, int lane,
                                      int m0, int n0, float (&acc)[2][4][4]) {
    constexpr int ST = KT * 2 + 16;
    const uint32_t lrow = (uint32_t)(lane & 15);
    const uint32_t lhi = (uint32_t)(lane >> 4) * 16u;
    const uint32_t aB0 = sA + (m0 + lrow) * ST + lhi;
    const uint32_t aB1 = aB0 + 16 * ST;
    const uint32_t bB0 = sB + (n0 + lrow) * ST + lhi;
    const uint32_t bB1 = bB0 + 16 * ST;
#pragma unroll
    for (int kc = 0; kc < KT / 16; kc++) {
        const uint32_t ko = kc * 32;
        uint32_t a0[4], a1[4], b0[4], b1[4];
        ldsm4(a0, aB0 + ko);
        ldsm4(a1, aB1 + ko);
        ldsm4(b0, bB0 + ko);
        ldsm4(b1, bB1 + ko);
        uint32_t be0[2] = {b0[0], b0[2]}, bo0[2] = {b0[1], b0[3]};
        uint32_t be1[2] = {b1[0], b1[2]}, bo1[2] = {b1[1], b1[3]};
        mma16816(acc[0][0], a0, be0); mma16816(acc[1][0], a1, be0);
        mma16816(acc[0][1], a0, bo0); mma16816(acc[1][1], a1, bo0);
        mma16816(acc[0][2], a0, be1); mma16816(acc[1][2], a1, be1);
        mma16816(acc[0][3], a0, bo1); mma16816(acc[1][3], a1, bo1);
    }
}

// ============================================================================
// Fused kernel
// ============================================================================
constexpr int ST128 = 272;
constexpr int TILE128 = 128 * ST128;   // 34816 B

__global__ void __launch_bounds__(512, 1) lstm_fused(float* __restrict__ out) {
    extern __shared__ __align__(128) char dsm[];
    __shared__ float s_b0[512], s_b1[512], s_mug[512], s_fcw[128];
    __shared__ float s_fc[4][128];

    const int tid = threadIdx.x, lane = tid & 31, wid = tid >> 5;
    const int rg = wid >> 2, cg = wid & 3, q = lane & 3;
    const int row0 = blockIdx.x * 128;
    const int m0 = rg * 32, n0 = cg * 32;

    const uint32_t s0 = smem_u32(dsm);
    const uint32_t sH1 = s0, sH2 = s0 + TILE128, sH1p = s0 + 2 * TILE128;
    const uint32_t sX = sH1p;                     // overlay: x dead before h1p written
    const uint32_t sB[2] = {s0 + 3 * TILE128, s0 + 4 * TILE128};

    // bias / mug / fcw into SMEM
    s_b0[tid] = d_bias0p[tid];
    if (tid < 512) { s_b1[tid] = d_bias1p[tid]; s_mug[tid] = d_mug[(row0 >> 10) * 512 + tid]; }
    if (tid < 128) s_fcw[tid] = d_fcw[tid];

    // prologue: x tile + first weight tile
    cp_fill<64>(sX, d_x16, row0, tid);
    cp_fill<64>(sB[0], d_W0i, 0, tid);
    CP_COMMIT();

    uint32_t creg[4][4];                          // c as half2, [nc][mt*2+h2]
    int bi = 0;

    // ---- epilogue macro-ish lambda ----
    auto epi = [&](const float (&acc)[2][4][4], int MODE, const float* addv,
                   uint32_t sDst, int nc, float* fcacc) {
#pragma unroll
        for (int mt = 0; mt < 2; mt++) {
#pragma unroll
            for (int h2 = 0; h2 < 2; h2++) {
                const int rowL = rg * 32 + mt * 16 + (lane >> 2) + h2 * 8;
                const int s = mt * 2 + h2;
                float cprev[2] = {0.0f, 0.0f};
                if (MODE == 2 || MODE == 4) {
                    __half2 cp2 = *reinterpret_cast<__half2*>(&creg[nc][s]);
                    cprev[0] = __low2float(cp2);
                    cprev[1] = __high2float(cp2);
                }
                float hv[2], cv[2];
#pragma unroll
                for (int u = 0; u < 2; u++) {
                    const int bcol = cg * 32 + 2 * q + u;
                    float gi = acc[mt][0][h2 * 2 + u] + addv[bcol];
                    float gf = acc[mt][1][h2 * 2 + u] + addv[bcol + 8];
                    float gg = acc[mt][2][h2 * 2 + u] + addv[bcol + 16];
                    float go = acc[mt][3][h2 * 2 + u] + addv[bcol + 24];
                    float cn;
                    if (MODE == 1 || MODE == 3)
                        cn = sigm_f(gi) * tanh_f(gg);
                    else
                        cn = sigm_f(gf) * cprev[u] + sigm_f(gi) * tanh_f(gg);
                    hv[u] = sigm_f(go) * tanh_f(cn);
                    cv[u] = cn;
                }
                if (MODE == 4) {
                    const int j0 = nc * 32 + cg * 8 + 2 * q;
                    fcacc[s] = fmaf(fmaxf(hv[0], 0.0f), s_fcw[j0], fcacc[s]);
                    fcacc[s] = fmaf(fmaxf(hv[1], 0.0f), s_fcw[j0 + 1], fcacc[s]);
                } else {
                    __half2 hh = __floats2half2_rn(hv[0], hv[1]);
                    uint32_t addr = sDst + (uint32_t)rowL * ST128
                                  + (uint32_t)(nc * 32 + cg * 8 + 2 * q) * 2;
                    asm volatile("st.shared.b32 [%0], %1;"
                                 :: "r"(addr), "r"(*reinterpret_cast<uint32_t*>(&hh)));
                    if (MODE == 1 || MODE == 3) {
                        __half2 cc = __floats2half2_rn(cv[0], cv[1]);
                        creg[nc][s] = *reinterpret_cast<uint32_t*>(&cc);
                    }
                }
            }
        }
    };

    // ---------------- stage 1 (K=64): x -> h1, c1 ----------------
#pragma unroll
    for (int nc = 0; nc < 4; nc++) {
        CP_WAIT0(); __syncthreads();
        if (nc < 3) cp_fill<64>(sB[bi ^ 1], d_W0i + (nc + 1) * 128 * 64, 0, tid);
        else        cp_fill<128>(sB[bi ^ 1], d_W0h, 0, tid);
        CP_COMMIT();
        float acc[2][4][4] = {};
        sweep<64>(sX, sB[bi], lane, m0, n0, acc);
        epi(acc, 1, s_b0 + nc * 128, sH1, nc, nullptr);
        bi ^= 1;
    }

    // ---------------- stage 2 (K=128): h1 -> h2 (uses c1) ----------------
#pragma unroll
    for (int nc = 0; nc < 4; nc++) {
        CP_WAIT0(); __syncthreads();
        if (nc < 3) cp_fill<128>(sB[bi ^ 1], d_W0h + (nc + 1) * 128 * 128, 0, tid);
        else        cp_fill<128>(sB[bi ^ 1], d_W1i, 0, tid);
        CP_COMMIT();
        float acc[2][4][4] = {};
        sweep<128>(sH1, sB[bi], lane, m0, n0, acc);
        epi(acc, 2, s_mug + nc * 128, sH2, nc, nullptr);
        bi ^= 1;
    }

    // ---------------- stage 3 (K=128): h1 -> h1p, c1p ----------------
#pragma unroll
    for (int nc = 0; nc < 4; nc++) {
        CP_WAIT0(); __syncthreads();
        if (nc < 3) cp_fill<128>(sB[bi ^ 1], d_W1i + (nc + 1) * 128 * 128, 0, tid);
        else        cp_fill<128>(sB[bi ^ 1], d_W1i, 0, tid);       // stage4 tile 0
        CP_COMMIT();
        float acc[2][4][4] = {};
        sweep<128>(sH1, sB[bi], lane, m0, n0, acc);
        epi(acc, 3, s_b1 + nc * 128, sH1p, nc, nullptr);
        bi ^= 1;
    }

    // ---------------- stage 4 (K=256): h2@W1i + h1p@W1h -> relu -> FC ----------------
    float fcacc[4] = {0.0f, 0.0f, 0.0f, 0.0f};
    float acc4[2][4][4];
#pragma unroll
    for (int t = 0; t < 8; t++) {
        CP_WAIT0(); __syncthreads();
        if (t < 7) {
            const int nt = t + 1;
            const __half* p = (nt & 1) ? (d_W1h + (nt >> 1) * 128 * 128)
                                       : (d_W1i + (nt >> 1) * 128 * 128);
            cp_fill<128>(sB[bi ^ 1], p, 0, tid);
            CP_COMMIT();
        }
        if ((t & 1) == 0) {
#pragma unroll
            for (int a = 0; a < 2; a++)
#pragma unroll
                for (int b = 0; b < 4; b++)
#pragma unroll
                    for (int c = 0; c < 4; c++) acc4[a][b][c] = 0.0f;
        }
        sweep<128>((t & 1) ? sH1p : sH2, sB[bi], lane, m0, n0, acc4);
        if (t & 1) epi(acc4, 4, s_b1 + (t >> 1) * 128, 0, t >> 1, fcacc);
        bi ^= 1;
    }

    // ---- FC reduce: shuffle over q, then cross-cg via SMEM ----
#pragma unroll
    for (int s = 0; s < 4; s++) {
        float v = fcacc[s];
        v += __shfl_xor_sync(0xffffffffu, v, 1);
        v += __shfl_xor_sync(0xffffffffu, v, 2);
        if (q == 0) {
            const int rowL = rg * 32 + (s >> 1) * 16 + (lane >> 2) + (s & 1) * 8;
            s_fc[cg][rowL] = v;
        }
    }
    __syncthreads();
    if (tid < 128)
        out[row0 + tid] = s_fc[0][tid] + s_fc[1][tid] + s_fc[2][tid] + s_fc[3][tid] + d_fcb_v;
}

// ============================================================================
// Launch
// ============================================================================
extern "C" void kernel_launch(void* const* d_in, const int* in_sizes, int n_in,
                              void* d_out, int out_size) {
    const float* x    = (const float*)d_in[0];
    const float* mu   = (const float*)d_in[1];
    const float* Wih0 = (const float*)d_in[2];
    const float* Whh0 = (const float*)d_in[3];
    const float* bih0 = (const float*)d_in[4];
    const float* bhh0 = (const float*)d_in[5];
    const float* Wih1 = (const float*)d_in[6];
    const float* Whh1 = (const float*)d_in[7];
    const float* bih1 = (const float*)d_in[8];
    const float* bhh1 = (const float*)d_in[9];
    const float* fcw  = (const float*)d_in[10];
    const float* fcb  = (const float*)d_in[11];
    float* out = (float*)d_out;

    const int SMEM = 5 * TILE128;   // 174080 B
    cudaFuncSetAttribute(lstm_fused, cudaFuncAttributeMaxDynamicSharedMemorySize, SMEM);

    prep_pack<<<256, 256>>>(Wih0, Whh0, Wih1, Whh1, bih0, bhh0, bih1, bhh1, fcw, fcb);
    prep_mug<<<64, 512>>>(mu, Wih0, bih0, bhh0);
    prep_x<<<4096, 256>>>(x);

    lstm_fused<<<512, 512, SMEM>>>(out);
}